// round 12
// baseline (speedup 1.0000x reference)
#include <cuda_runtime.h>
#include <cuda_fp16.h>
#include <cstdint>
#include <math.h>

#define B_   2
#define C_   256
#define H_   100
#define W_   152
#define HW_  (H_*W_)
#define P_   2
#define KB_  5          // bins
#define DEXP (P_*C_)    // 512

// ---------------- scratch (static device memory; no allocation) -------------
__device__ __half   g_efs_h[(size_t)B_*HW_*DEXP];   // ef fp16 (GEMM2 A + gather src)
__device__ __half   g_out_h[(size_t)B_*HW_*DEXP];   // gather out fp16 (GEMM3 B)
__device__ __half   g_xs_h [(size_t)B_*HW_*C_];     // x transposed fp16 (GEMM1 A)
#define WOFF_EF   0
#define WOFF_HM1  (DEXP*C_)                  // 131072
__device__ __half   g_w_h  [DEXP*C_ + P_*C_*C_];    // ef_w, hm1_w fp16 (B operands)
__device__ __half   g_mw_h [C_*DEXP];               // merge_w fp16 (GEMM3 A)
__device__ float g_heat [B_*P_*HW_];
__device__ float g_hacc [B_*P_*HW_];
__device__ float g_merged[(size_t)B_*C_*HW_];
__device__ float g_stat2[B_*32*2];           // (b,g) -> sum, sumsq (atomic)

// ======================= helpers =============================================
__device__ __forceinline__ uint32_t smem_u32(const void* p) {
    uint32_t a;
    asm("{ .reg .u64 t; cvta.to.shared.u64 t, %1; cvt.u32.u64 %0, t; }" : "=r"(a) : "l"(p));
    return a;
}
__device__ __forceinline__ void ldsm_x4(uint32_t* r, uint32_t a) {
    asm volatile("ldmatrix.sync.aligned.m8n8.x4.shared.b16 {%0,%1,%2,%3}, [%4];"
        : "=r"(r[0]), "=r"(r[1]), "=r"(r[2]), "=r"(r[3]) : "r"(a));
}
__device__ __forceinline__ void mma_f16(float* d, const uint32_t* a, const uint32_t* b) {
    asm volatile("mma.sync.aligned.m16n8k16.row.col.f32.f16.f16.f32 "
        "{%0,%1,%2,%3}, {%4,%5,%6,%7}, {%8,%9}, {%0,%1,%2,%3};"
        : "+f"(d[0]), "+f"(d[1]), "+f"(d[2]), "+f"(d[3])
        : "r"(a[0]), "r"(a[1]), "r"(a[2]), "r"(a[3]), "r"(b[0]), "r"(b[1]));
}
__device__ __forceinline__ void cp_async16(uint32_t dst, const void* src, int src_bytes) {
    asm volatile("cp.async.cg.shared.global [%0], [%1], 16, %2;"
        :: "r"(dst), "l"(src), "r"(src_bytes) : "memory");
}
#define CP_COMMIT() asm volatile("cp.async.commit_group;" ::: "memory")
#define CP_WAIT(n)  asm volatile("cp.async.wait_group %0;" :: "n"(n) : "memory")

// ================= single-pass fp16 mma.sync GEMM ============================
// D[M,N] = A[M,K] * B[N,K]^T;  A, B plain fp16 planes, K-major.
// 256x128 CTA tile, warp tile 64x64 (4 M-warps x 2 N-warps), 1 CTA/SM.
// MMA:ldsm = 4.0 per K-step (was 2.67).
// EPI: 0/3 = fp32 C (+bias); 3 adds atomic GN sums (GEMM3);
//      1 = fp16 C plane ONLY (GEMM1);
//      2 = no C store; heat fusion: atomicAdd( sum_n relu(c+bias)*w2[n] ).
#define GBM 256
#define GBN 128
#define GBK 32
#define ROWB   80                  // smem row pitch (odd 16B stride -> LDSM conflict-free)
#define ATILE_B (256*ROWB)         // 20480
#define BTILE_B (128*ROWB)         // 10240
#define BUF_B  (ATILE_B + BTILE_B) // 30720
#define NSTAGE 3
#define GEMM_SMEM (NSTAGE*BUF_B)   // 92160 B

template<int BIAS_MODE, int EPI>
__global__ __launch_bounds__(256, 1)
void tc_gemm(const __half* __restrict__ Ahp, int lda, long sA1, long sA2,
             const __half* __restrict__ Bhp, int ldb, long sB1, long sB2,
             float* __restrict__ Cm, int ldc, long sC1, long sC2,
             const float* __restrict__ bias, long sb1, long sb2,
             __half* __restrict__ Ch,
             const float* __restrict__ w2, float* __restrict__ aux,
             int zdiv, int M, int N, int K)
{
    extern __shared__ char smem[];
    const uint32_t sbase = smem_u32(smem);
    const int tid = threadIdx.x;
    const int lane = tid & 31, wid = tid >> 5;

    const int z = blockIdx.z;
    const int z1 = z / zdiv, z2 = z % zdiv;
    Ahp += z1 * sA1 + z2 * sA2;
    Bhp += z1 * sB1 + z2 * sB2;
    const float* bptr = bias + z1 * sb1 + z2 * sb2;

    const int m0 = blockIdx.y * GBM;
    const int n0 = blockIdx.x * GBN;

    const int wm = wid & 3;          // 4 warps over M (64 rows each)
    const int wn = wid >> 2;         // 2 warps over N (64 cols each)
    const int lane8 = lane & 7, sel = lane >> 3;

    float acc[4][8][4];
#pragma unroll
    for (int i = 0; i < 4; i++)
#pragma unroll
        for (int j = 0; j < 8; j++)
#pragma unroll
            for (int q = 0; q < 4; q++) acc[i][j][q] = 0.f;

    const int nk = K / GBK;

    auto LOADCP = [&](int kt, int stage) {
        const int k0 = kt * GBK;
        const uint32_t sb = sbase + stage * BUF_B;
        // A: 256 rows x 4 quads = 1024 cp (4 per thread)
#pragma unroll
        for (int j = 0; j < 4; j++) {
            int idx = tid + j * 256;
            int row = idx >> 2, q = idx & 3;
            int gm = m0 + row;
            int sz = (gm < M) ? 16 : 0;
            long ga = (long)(gm < M ? gm : M - 1) * lda + k0 + q * 8;
            cp_async16(sb + (uint32_t)(row * ROWB + q * 16), Ahp + ga, sz);
        }
        // B: 128 rows x 4 quads = 512 cp (2 per thread)
#pragma unroll
        for (int j = 0; j < 2; j++) {
            int idx = tid + j * 256;
            int row = idx >> 2, q = idx & 3;
            int gn = n0 + row;
            int sz = (gn < N) ? 16 : 0;
            long gb = (long)(gn < N ? gn : N - 1) * ldb + k0 + q * 8;
            cp_async16(sb + ATILE_B + (uint32_t)(row * ROWB + q * 16), Bhp + gb, sz);
        }
    };

    auto COMPUTE = [&](int stage) {
        const uint32_t ah_b = sbase + stage * BUF_B;
        const uint32_t bh_b = ah_b + ATILE_B;
#pragma unroll
        for (int ks = 0; ks < 2; ks++) {
            const int kb = ks * 16;
            uint32_t ah[4][4];
#pragma unroll
            for (int mf = 0; mf < 4; mf++) {
                int row = wm * 64 + mf * 16 + lane8 + (sel & 1) * 8;
                int kc  = kb + (sel & 2) * 4;
                ldsm_x4(ah[mf], ah_b + (uint32_t)(row * ROWB + kc * 2));
            }
#pragma unroll
            for (int nf2 = 0; nf2 < 4; nf2++) {
                int nrow = wn * 64 + nf2 * 16 + lane8 + (sel & 2) * 4;
                int kc   = kb + (sel & 1) * 8;
                uint32_t bh4[4];
                ldsm_x4(bh4, bh_b + (uint32_t)(nrow * ROWB + kc * 2));
                // 8 distinct accumulators between reuses: latency hidden
#pragma unroll
                for (int half = 0; half < 2; half++)
#pragma unroll
                    for (int mf = 0; mf < 4; mf++)
                        mma_f16(acc[mf][nf2 * 2 + half], ah[mf], bh4 + half * 2);
            }
        }
    };

    // 3-stage pipeline, one barrier per K-tile
    LOADCP(0, 0); CP_COMMIT();
    if (nk > 1) { LOADCP(1, 1); CP_COMMIT(); }
    int stage = 0;
    for (int kt = 0; kt < nk; kt++) {
        if (kt + 1 < nk) { CP_WAIT(1); } else { CP_WAIT(0); }
        __syncthreads();
        if (kt + 2 < nk) {
            int s2 = stage + 2; if (s2 >= NSTAGE) s2 -= NSTAGE;
            LOADCP(kt + 2, s2); CP_COMMIT();
        }
        COMPUTE(stage);
        if (++stage == NSTAGE) stage = 0;
    }

    // ---- epilogue ----
    const int g = lane >> 2, t = lane & 3;

    if (EPI == 2) {
        const float* w2p = w2 + z2 * C_;
        float s[4][2] = {{0.f,0.f},{0.f,0.f},{0.f,0.f},{0.f,0.f}};
#pragma unroll
        for (int nf = 0; nf < 8; nf++) {
            int gn = n0 + wn * 64 + nf * 8 + 2 * t;
            float b0 = bptr[gn], b1 = bptr[gn + 1];
            float w0 = w2p[gn],  w1 = w2p[gn + 1];
#pragma unroll
            for (int mf = 0; mf < 4; mf++)
#pragma unroll
                for (int rr = 0; rr < 2; rr++) {
                    float v0 = fmaxf(acc[mf][nf][rr * 2 + 0] + b0, 0.f);
                    float v1 = fmaxf(acc[mf][nf][rr * 2 + 1] + b1, 0.f);
                    s[mf][rr] += v0 * w0 + v1 * w1;
                }
        }
#pragma unroll
        for (int mf = 0; mf < 4; mf++)
#pragma unroll
            for (int rr = 0; rr < 2; rr++) {
                s[mf][rr] += __shfl_xor_sync(0xffffffffu, s[mf][rr], 1);
                s[mf][rr] += __shfl_xor_sync(0xffffffffu, s[mf][rr], 2);
            }
        if (t == 0) {
            float* hz = aux + (long)z * HW_;
#pragma unroll
            for (int mf = 0; mf < 4; mf++)
#pragma unroll
                for (int rr = 0; rr < 2; rr++) {
                    int gm = m0 + wm * 64 + mf * 16 + rr * 8 + g;
                    if (gm < M) atomicAdd(hz + gm, s[mf][rr]);
                }
        }
        return;
    }

    if (EPI != 1) Cm += z1 * sC1 + z2 * sC2;
    if (EPI == 1) Ch += z1 * sC1 + z2 * sC2;

    float gs[4][2]  = {{0.f,0.f},{0.f,0.f},{0.f,0.f},{0.f,0.f}};
    float gs2[4][2] = {{0.f,0.f},{0.f,0.f},{0.f,0.f},{0.f,0.f}};

#pragma unroll
    for (int mf = 0; mf < 4; mf++) {
#pragma unroll
        for (int nf = 0; nf < 8; nf++) {
            const float* d = acc[mf][nf];
            int gm0 = m0 + wm * 64 + mf * 16 + g;
            int gn  = n0 + wn * 64 + nf * 8 + 2 * t;
            if (gn >= N) continue;
            float bc0 = 0.f, bc1 = 0.f;
            if (BIAS_MODE == 1) { bc0 = bptr[gn]; bc1 = bptr[gn + 1]; }
#pragma unroll
            for (int rr = 0; rr < 2; rr++) {
                int gm = gm0 + rr * 8;
                if (gm >= M) continue;
                float v0 = d[rr * 2 + 0], v1 = d[rr * 2 + 1];
                if (BIAS_MODE == 1) { v0 += bc0; v1 += bc1; }
                else { float br = bptr[gm]; v0 += br; v1 += br; }
                long idx = (long)gm * ldc + gn;
                if (EPI == 1) {
                    __half h0 = __float2half_rn(v0), h1 = __float2half_rn(v1);
                    *reinterpret_cast<uint32_t*>(Ch + idx) =
                        (uint32_t)__half_as_ushort(h0) | ((uint32_t)__half_as_ushort(h1) << 16);
                } else {
                    *reinterpret_cast<float2*>(Cm + idx) = make_float2(v0, v1);
                }
                if (EPI == 3) {
                    gs[mf][rr]  += v0 + v1;
                    gs2[mf][rr] += v0 * v0 + v1 * v1;
                }
            }
        }
    }

    if (EPI == 3) {
#pragma unroll
        for (int mf = 0; mf < 4; mf++)
#pragma unroll
            for (int rr = 0; rr < 2; rr++) {
#pragma unroll
                for (int o = 16; o; o >>= 1) {
                    gs[mf][rr]  += __shfl_xor_sync(0xffffffffu, gs[mf][rr],  o);
                    gs2[mf][rr] += __shfl_xor_sync(0xffffffffu, gs2[mf][rr], o);
                }
                if (lane == 0) {
                    int gidx = (m0 + wm * 64 + mf * 16 + rr * 8) >> 3;   // 0..31
                    atomicAdd(aux + (z1 * 32 + gidx) * 2 + 0, gs[mf][rr]);
                    atomicAdd(aux + (z1 * 32 + gidx) * 2 + 1, gs2[mf][rr]);
                }
            }
    }
}

// ---------------- prep: convert weights + zero accumulators ------------------
__global__ void prep_kernel(const float* __restrict__ ef_w,
                            const float* __restrict__ hm1_w,
                            const float* __restrict__ merge_w,
                            __half* __restrict__ w_h,
                            __half* __restrict__ mw_h,
                            float* __restrict__ hacc, float* __restrict__ stat2)
{
    int i = blockIdx.x * 256 + threadIdx.x;
    if (i < DEXP * C_)    w_h[WOFF_EF + i]  = __float2half_rn(ef_w[i]);
    if (i < P_ * C_ * C_) w_h[WOFF_HM1 + i] = __float2half_rn(hm1_w[i]);
    if (i < C_ * DEXP)    mw_h[i] = __float2half_rn(merge_w[i]);
    if (i < B_ * P_ * HW_) hacc[i] = 0.f;
    if (i < B_ * 32 * 2)   stat2[i] = 0.f;
}

// -------- transpose x (B,C,HW) -> fp16 plane (B,HW,C), packed stores ---------
__global__ void split_x_kernel(const float* __restrict__ x, __half* __restrict__ xh)
{
    __shared__ float tile[32][33];
    int b = blockIdx.z;
    int hw0 = blockIdx.x * 32, c0 = blockIdx.y * 32;
    const float* xb = x + (long)b * C_ * HW_;
    int tx = threadIdx.x, ty = threadIdx.y;   // 32 x 8
#pragma unroll
    for (int i = 0; i < 32; i += 8) {
        int c = c0 + ty + i, hw = hw0 + tx;
        tile[ty + i][tx] = (hw < HW_) ? xb[(long)c * HW_ + hw] : 0.f;
    }
    __syncthreads();
    int tid = ty * 32 + tx;
    int cpair = tid & 15;          // 16 c-pairs
    int hwl0  = tid >> 4;          // 0..15
#pragma unroll
    for (int rep = 0; rep < 2; rep++) {
        int hwl = hwl0 + rep * 16;
        int hw = hw0 + hwl;
        if (hw < HW_) {
            __half h0 = __float2half_rn(tile[2 * cpair + 0][hwl]);
            __half h1 = __float2half_rn(tile[2 * cpair + 1][hwl]);
            long idx = (long)b * HW_ * C_ + (long)hw * C_ + c0 + 2 * cpair;
            *reinterpret_cast<uint32_t*>(xh + idx) =
                (uint32_t)__half_as_ushort(h0) | ((uint32_t)__half_as_ushort(h1) << 16);
        }
    }
}

__global__ void heat_exp_kernel(const float* __restrict__ hacc,
                                const float* __restrict__ hm2_b,
                                float* __restrict__ heat)
{
    int i = blockIdx.x * 256 + threadIdx.x;
    if (i >= B_ * P_ * HW_) return;
    int p = (i / HW_) % P_;
    heat[i] = expf(hacc[i] + hm2_b[p]);
}

// --------- deformable bilinear gather: samples fp16 ef plane -----------------
__global__ void sample_kernel(const __half* __restrict__ efs,  // (B, HW, 512) fp16
                              const float* __restrict__ heat,  // (B*P, HW)
                              const float* __restrict__ offs,  // (B, P*KB*2, HW)
                              __half* __restrict__ oh)         // fp16 out (B,HW,512)
{
    int gw = (blockIdx.x * blockDim.x + threadIdx.x) >> 5;
    int lane = threadIdx.x & 31;
    if (gw >= B_ * P_ * HW_) return;
    int i  = gw % HW_;
    int bp = gw / HW_;
    int p  = bp % P_;
    int b  = bp / P_;
    int y = i / W_, x = i % W_;

    float n[8];
#pragma unroll
    for (int j = 0; j < 8; j++) n[j] = 0.f;
    float den = 0.f;

    const uint4* efb = reinterpret_cast<const uint4*>(
        efs + ((long)b * HW_) * DEXP + p * C_ + lane * 8);
    const float* heatb = heat + (long)bp * HW_;
    const float* offb  = offs + ((long)b * (P_ * KB_ * 2) + p * KB_ * 2) * HW_;

#pragma unroll
    for (int k = 0; k < KB_; k++) {
        float ys = (float)y + offb[(k * 2 + 0) * HW_ + i];
        float xs = (float)x + offb[(k * 2 + 1) * HW_ + i];
        float y0f = floorf(ys), x0f = floorf(xs);
#pragma unroll
        for (int c4 = 0; c4 < 4; c4++) {
            float yi = y0f + (float)(c4 >> 1);
            float xi = x0f + (float)(c4 & 1);
            if (yi < 0.f || yi > (float)(H_ - 1) || xi < 0.f || xi > (float)(W_ - 1))
                continue;
            float w = (1.f - fabsf(ys - yi)) * (1.f - fabsf(xs - xi));
            int src = (int)yi * W_ + (int)xi;
            float wh = w * heatb[src];
            den += wh;
            uint4 u = efb[(long)src * (DEXP / 8)];
            float2 f0 = __half22float2(*reinterpret_cast<__half2*>(&u.x));
            float2 f1 = __half22float2(*reinterpret_cast<__half2*>(&u.y));
            float2 f2 = __half22float2(*reinterpret_cast<__half2*>(&u.z));
            float2 f3 = __half22float2(*reinterpret_cast<__half2*>(&u.w));
            n[0] += wh * f0.x; n[1] += wh * f0.y;
            n[2] += wh * f1.x; n[3] += wh * f1.y;
            n[4] += wh * f2.x; n[5] += wh * f2.y;
            n[6] += wh * f3.x; n[7] += wh * f3.y;
        }
    }
    float inv = 1.f / (den + 1e-6f);
    unsigned short hh[8];
#pragma unroll
    for (int j = 0; j < 8; j++) hh[j] = __half_as_ushort(__float2half_rn(n[j] * inv));
    uint4 ph;
    ph.x = (uint32_t)hh[0] | ((uint32_t)hh[1] << 16);
    ph.y = (uint32_t)hh[2] | ((uint32_t)hh[3] << 16);
    ph.z = (uint32_t)hh[4] | ((uint32_t)hh[5] << 16);
    ph.w = (uint32_t)hh[6] | ((uint32_t)hh[7] << 16);
    long obase = ((long)b * HW_ + i) * DEXP + p * C_ + lane * 8;
    *reinterpret_cast<uint4*>(oh + obase) = ph;
}

// ---------------- GroupNorm finalize (float4, stats precomputed) -------------
__global__ void gn_norm(const float* __restrict__ merged,
                        const float* __restrict__ stat2,
                        const float* __restrict__ gn_g,
                        const float* __restrict__ gn_b,
                        float* __restrict__ out)
{
    long i4 = (long)blockIdx.x * 256 + threadIdx.x;
    const long total4 = (long)B_ * C_ * HW_ / 4;
    if (i4 >= total4) return;
    long idx = i4 * 4;
    int c = (int)((idx / HW_) % C_);
    int b = (int)(idx / ((long)C_ * HW_));
    int g = c >> 3;
    const float n = 8.f * HW_;
    float s  = stat2[(b * 32 + g) * 2 + 0];
    float s2 = stat2[(b * 32 + g) * 2 + 1];
    float mu   = s / n;
    float var  = s2 / n - mu * mu;
    float rstd = rsqrtf(var + 1e-5f);
    float sc = rstd * gn_g[c];
    float sh = gn_b[c] - mu * sc;
    float4 v = *reinterpret_cast<const float4*>(merged + idx);
    float4 r;
    r.x = fmaxf(v.x * sc + sh, 0.f);
    r.y = fmaxf(v.y * sc + sh, 0.f);
    r.z = fmaxf(v.z * sc + sh, 0.f);
    r.w = fmaxf(v.w * sc + sh, 0.f);
    *reinterpret_cast<float4*>(out + idx) = r;
}

// ---------------- launch ------------------------------------------------------
extern "C" void kernel_launch(void* const* d_in, const int* in_sizes, int n_in,
                              void* d_out, int out_size)
{
    const float* x       = (const float*)d_in[0];
    const float* offsets = (const float*)d_in[1];
    const float* ef_w    = (const float*)d_in[2];
    const float* ef_b    = (const float*)d_in[3];
    const float* hm1_w   = (const float*)d_in[4];
    const float* hm1_b   = (const float*)d_in[5];
    const float* hm2_w   = (const float*)d_in[6];
    const float* hm2_b   = (const float*)d_in[7];
    const float* merge_w = (const float*)d_in[8];
    const float* merge_b = (const float*)d_in[9];
    const float* gn_g    = (const float*)d_in[10];
    const float* gn_b    = (const float*)d_in[11];
    float* out = (float*)d_out;

    float *heat, *hacc, *merged, *stat2;
    __half *efs_h, *out_h, *xs_h, *w_h, *mw_h;
    cudaGetSymbolAddress((void**)&efs_h,  g_efs_h);
    cudaGetSymbolAddress((void**)&out_h,  g_out_h);
    cudaGetSymbolAddress((void**)&xs_h,   g_xs_h);
    cudaGetSymbolAddress((void**)&w_h,    g_w_h);
    cudaGetSymbolAddress((void**)&mw_h,   g_mw_h);
    cudaGetSymbolAddress((void**)&heat,   g_heat);
    cudaGetSymbolAddress((void**)&hacc,   g_hacc);
    cudaGetSymbolAddress((void**)&merged, g_merged);
    cudaGetSymbolAddress((void**)&stat2,  g_stat2);

    cudaFuncSetAttribute(tc_gemm<1, 1>, cudaFuncAttributeMaxDynamicSharedMemorySize, GEMM_SMEM);
    cudaFuncSetAttribute(tc_gemm<1, 2>, cudaFuncAttributeMaxDynamicSharedMemorySize, GEMM_SMEM);
    cudaFuncSetAttribute(tc_gemm<2, 3>, cudaFuncAttributeMaxDynamicSharedMemorySize, GEMM_SMEM);

    // 0) prep: weight conversion + zeroing; x transpose->fp16
    prep_kernel<<<(DEXP * C_ + 255) / 256, 256>>>(ef_w, hm1_w, merge_w,
                                                  w_h, mw_h, hacc, stat2);
    {
        dim3 grid((HW_ + 31) / 32, C_ / 32, B_);
        split_x_kernel<<<grid, dim3(32, 8)>>>(x, xs_h);
    }

    // 1) GEMM1: efs[b][i][d] = fp16( sum_c xT[b][i][c]*ef_w[d][c] + ef_b[d] )
    {
        dim3 grid(DEXP / GBN, (HW_ + GBM - 1) / GBM, B_);
        tc_gemm<1, 1><<<grid, 256, GEMM_SMEM>>>(
            xs_h, C_, (long)HW_ * C_, 0,
            w_h + WOFF_EF, C_, 0, 0,
            nullptr, DEXP, (long)HW_ * DEXP, 0,
            ef_b, 0, 0,
            efs_h, nullptr, nullptr,
            1, HW_, DEXP, C_);
    }

    // 2) GEMM2 + heat fusion
    {
        dim3 grid(C_ / GBN, (HW_ + GBM - 1) / GBM, B_ * P_);
        tc_gemm<1, 2><<<grid, 256, GEMM_SMEM>>>(
            efs_h, DEXP, (long)HW_ * DEXP, (long)C_,
            w_h + WOFF_HM1, C_, 0, (long)C_ * C_,
            nullptr, 0, 0, 0,
            hm1_b, 0, (long)C_,
            nullptr, hm2_w, hacc,
            P_, HW_, C_, C_);
    }

    // 3) heat = exp(hacc + hm2_b)
    heat_exp_kernel<<<(B_ * P_ * HW_ + 255) / 256, 256>>>(hacc, hm2_b, heat);

    // 4) gather (fp16 source) -> fp16 outs
    {
        int warps = B_ * P_ * HW_;
        sample_kernel<<<(warps * 32 + 255) / 256, 256>>>(efs_h, heat, offsets, out_h);
    }

    // 5) GEMM3 + GN stats: M=256 (one M-tile), N=HW
    {
        dim3 grid((HW_ + GBN - 1) / GBN, (C_ + GBM - 1) / GBM, B_);
        tc_gemm<2, 3><<<grid, 256, GEMM_SMEM>>>(
            mw_h, DEXP, 0, 0,
            out_h, DEXP, (long)HW_ * DEXP, 0,
            merged, HW_, (long)C_ * HW_, 0,
            merge_b, 0, 0,
            nullptr, nullptr, stat2,
            1, C_, HW_, DEXP);
    }

    // 6) GroupNorm finalize + ReLU
    {
        long total4 = (long)B_ * C_ * HW_ / 4;
        gn_norm<<<(int)((total4 + 255) / 256), 256>>>(merged, stat2, gn_g, gn_b, out);
    }
}

// round 13
// speedup vs baseline: 1.1529x; 1.1529x over previous
#include <cuda_runtime.h>
#include <cuda_fp16.h>
#include <cstdint>
#include <math.h>

#define B_   2
#define C_   256
#define H_   100
#define W_   152
#define HW_  (H_*W_)
#define P_   2
#define KB_  5          // bins
#define DEXP (P_*C_)    // 512

// ---------------- scratch (static device memory; no allocation) -------------
__device__ __half   g_efs_h[(size_t)B_*HW_*DEXP];   // ef fp16 (GEMM2 A + gather src)
__device__ __half   g_out_h[(size_t)B_*HW_*DEXP];   // gather out fp16 (GEMM3 B)
__device__ __half   g_xs_h [(size_t)B_*HW_*C_];     // x transposed fp16 (GEMM1 A)
#define WOFF_EF   0
#define WOFF_HM1  (DEXP*C_)                  // 131072
__device__ __half   g_w_h  [DEXP*C_ + P_*C_*C_];    // ef_w, hm1_w fp16 (B operands)
__device__ __half   g_mw_h [C_*DEXP];               // merge_w fp16 (GEMM3 A)
__device__ float g_heat [B_*P_*HW_];
__device__ float g_hacc [B_*P_*HW_];
__device__ float g_merged[(size_t)B_*C_*HW_];
__device__ float g_stat2[B_*32*2];           // (b,g) -> sum, sumsq (atomic)

// ======================= helpers =============================================
__device__ __forceinline__ uint32_t smem_u32(const void* p) {
    uint32_t a;
    asm("{ .reg .u64 t; cvta.to.shared.u64 t, %1; cvt.u32.u64 %0, t; }" : "=r"(a) : "l"(p));
    return a;
}
__device__ __forceinline__ void ldsm_x4(uint32_t* r, uint32_t a) {
    asm volatile("ldmatrix.sync.aligned.m8n8.x4.shared.b16 {%0,%1,%2,%3}, [%4];"
        : "=r"(r[0]), "=r"(r[1]), "=r"(r[2]), "=r"(r[3]) : "r"(a));
}
__device__ __forceinline__ void mma_f16(float* d, const uint32_t* a, const uint32_t* b) {
    asm volatile("mma.sync.aligned.m16n8k16.row.col.f32.f16.f16.f32 "
        "{%0,%1,%2,%3}, {%4,%5,%6,%7}, {%8,%9}, {%0,%1,%2,%3};"
        : "+f"(d[0]), "+f"(d[1]), "+f"(d[2]), "+f"(d[3])
        : "r"(a[0]), "r"(a[1]), "r"(a[2]), "r"(a[3]), "r"(b[0]), "r"(b[1]));
}
__device__ __forceinline__ void cp_async16(uint32_t dst, const void* src, int src_bytes) {
    asm volatile("cp.async.cg.shared.global [%0], [%1], 16, %2;"
        :: "r"(dst), "l"(src), "r"(src_bytes) : "memory");
}
#define CP_COMMIT() asm volatile("cp.async.commit_group;" ::: "memory")
#define CP_WAIT(n)  asm volatile("cp.async.wait_group %0;" :: "n"(n) : "memory")

// ================= single-pass fp16 mma.sync GEMM (R11 config, frozen) =======
// D[M,N] = A[M,K] * B[N,K]^T;  A, B plain fp16 planes, K-major.
// 128x128 CTA tile, warp tile 32x64 (4 M-warps x 2 N-warps), 2 CTAs/SM.
// 3-stage cp.async ring, one __syncthreads per K-tile.
// EPI: 0/3 = fp32 C (+bias); 3 adds atomic GN sums (GEMM3);
//      1 = fp16 C plane ONLY (GEMM1);
//      2 = no C store; heat fusion: atomicAdd( sum_n relu(c+bias)*w2[n] ).
#define GBM 128
#define GBN 128
#define GBK 32
#define ROWB   80                  // smem row pitch (odd 16B stride -> LDSM conflict-free)
#define ATILE_B (128*ROWB)         // 10240
#define BTILE_B (128*ROWB)         // 10240
#define BUF_B  (ATILE_B + BTILE_B) // 20480
#define NSTAGE 3
#define GEMM_SMEM (NSTAGE*BUF_B)   // 61440 B

template<int BIAS_MODE, int EPI>
__global__ __launch_bounds__(256, 2)
void tc_gemm(const __half* __restrict__ Ahp, int lda, long sA1, long sA2,
             const __half* __restrict__ Bhp, int ldb, long sB1, long sB2,
             float* __restrict__ Cm, int ldc, long sC1, long sC2,
             const float* __restrict__ bias, long sb1, long sb2,
             __half* __restrict__ Ch,
             const float* __restrict__ w2, float* __restrict__ aux,
             int zdiv, int M, int N, int K)
{
    extern __shared__ char smem[];
    const uint32_t sbase = smem_u32(smem);
    const int tid = threadIdx.x;
    const int lane = tid & 31, wid = tid >> 5;

    const int z = blockIdx.z;
    const int z1 = z / zdiv, z2 = z % zdiv;
    Ahp += z1 * sA1 + z2 * sA2;
    Bhp += z1 * sB1 + z2 * sB2;
    const float* bptr = bias + z1 * sb1 + z2 * sb2;

    const int m0 = blockIdx.y * GBM;
    const int n0 = blockIdx.x * GBN;

    const int wm = wid & 3;          // 4 warps over M (32 rows each)
    const int wn = wid >> 2;         // 2 warps over N (64 cols each)
    const int lane8 = lane & 7, sel = lane >> 3;

    float acc[2][8][4];
#pragma unroll
    for (int i = 0; i < 2; i++)
#pragma unroll
        for (int j = 0; j < 8; j++)
#pragma unroll
            for (int q = 0; q < 4; q++) acc[i][j][q] = 0.f;

    const int nk = K / GBK;

    auto LOADCP = [&](int kt, int stage) {
        const int k0 = kt * GBK;
        const uint32_t sb = sbase + stage * BUF_B;
#pragma unroll
        for (int j = 0; j < 2; j++) {
            int idx = tid + j * 256;           // 0..511
            int row = idx >> 2, q = idx & 3;
            uint32_t off = (uint32_t)(row * ROWB + q * 16);
            int gm = m0 + row, gn = n0 + row;
            int szA = (gm < M) ? 16 : 0;
            int szB = (gn < N) ? 16 : 0;
            long ga = (long)(gm < M ? gm : M - 1) * lda + k0 + q * 8;
            long gb = (long)(gn < N ? gn : N - 1) * ldb + k0 + q * 8;
            cp_async16(sb + off,           Ahp + ga, szA);
            cp_async16(sb + ATILE_B + off, Bhp + gb, szB);
        }
    };

    auto COMPUTE = [&](int stage) {
        const uint32_t ah_b = sbase + stage * BUF_B;
        const uint32_t bh_b = ah_b + ATILE_B;
#pragma unroll
        for (int ks = 0; ks < 2; ks++) {
            const int kb = ks * 16;
            uint32_t ah[2][4];
#pragma unroll
            for (int mf = 0; mf < 2; mf++) {
                int row = wm * 32 + mf * 16 + lane8 + (sel & 1) * 8;
                int kc  = kb + (sel & 2) * 4;
                ldsm_x4(ah[mf], ah_b + (uint32_t)(row * ROWB + kc * 2));
            }
#pragma unroll
            for (int nf2 = 0; nf2 < 4; nf2++) {
                int nrow = wn * 64 + nf2 * 16 + lane8 + (sel & 2) * 4;
                int kc   = kb + (sel & 1) * 8;
                uint32_t bh4[4];
                ldsm_x4(bh4, bh_b + (uint32_t)(nrow * ROWB + kc * 2));
#pragma unroll
                for (int half = 0; half < 2; half++)
#pragma unroll
                    for (int mf = 0; mf < 2; mf++)
                        mma_f16(acc[mf][nf2 * 2 + half], ah[mf], bh4 + half * 2);
            }
        }
    };

    // 3-stage pipeline, one barrier per K-tile
    LOADCP(0, 0); CP_COMMIT();
    if (nk > 1) { LOADCP(1, 1); CP_COMMIT(); }
    int stage = 0;
    for (int kt = 0; kt < nk; kt++) {
        if (kt + 1 < nk) { CP_WAIT(1); } else { CP_WAIT(0); }
        __syncthreads();
        if (kt + 2 < nk) {
            int s2 = stage + 2; if (s2 >= NSTAGE) s2 -= NSTAGE;
            LOADCP(kt + 2, s2); CP_COMMIT();
        }
        COMPUTE(stage);
        if (++stage == NSTAGE) stage = 0;
    }

    // ---- epilogue ----
    const int g = lane >> 2, t = lane & 3;

    if (EPI == 2) {
        const float* w2p = w2 + z2 * C_;
        float s[2][2] = {{0.f, 0.f}, {0.f, 0.f}};
#pragma unroll
        for (int nf = 0; nf < 8; nf++) {
            int gn = n0 + wn * 64 + nf * 8 + 2 * t;
            float b0 = bptr[gn], b1 = bptr[gn + 1];
            float w0 = w2p[gn],  w1 = w2p[gn + 1];
#pragma unroll
            for (int mf = 0; mf < 2; mf++)
#pragma unroll
                for (int rr = 0; rr < 2; rr++) {
                    float v0 = fmaxf(acc[mf][nf][rr * 2 + 0] + b0, 0.f);
                    float v1 = fmaxf(acc[mf][nf][rr * 2 + 1] + b1, 0.f);
                    s[mf][rr] += v0 * w0 + v1 * w1;
                }
        }
#pragma unroll
        for (int mf = 0; mf < 2; mf++)
#pragma unroll
            for (int rr = 0; rr < 2; rr++) {
                s[mf][rr] += __shfl_xor_sync(0xffffffffu, s[mf][rr], 1);
                s[mf][rr] += __shfl_xor_sync(0xffffffffu, s[mf][rr], 2);
            }
        if (t == 0) {
            float* hz = aux + (long)z * HW_;
#pragma unroll
            for (int mf = 0; mf < 2; mf++)
#pragma unroll
                for (int rr = 0; rr < 2; rr++) {
                    int gm = m0 + wm * 32 + mf * 16 + rr * 8 + g;
                    if (gm < M) atomicAdd(hz + gm, s[mf][rr]);
                }
        }
        return;
    }

    if (EPI != 1) Cm += z1 * sC1 + z2 * sC2;
    if (EPI == 1) Ch += z1 * sC1 + z2 * sC2;

    float gs[2][2]  = {{0.f, 0.f}, {0.f, 0.f}};
    float gs2[2][2] = {{0.f, 0.f}, {0.f, 0.f}};

#pragma unroll
    for (int mf = 0; mf < 2; mf++) {
#pragma unroll
        for (int nf = 0; nf < 8; nf++) {
            const float* d = acc[mf][nf];
            int gm0 = m0 + wm * 32 + mf * 16 + g;
            int gn  = n0 + wn * 64 + nf * 8 + 2 * t;
            if (gn >= N) continue;
            float bc0 = 0.f, bc1 = 0.f;
            if (BIAS_MODE == 1) { bc0 = bptr[gn]; bc1 = bptr[gn + 1]; }
#pragma unroll
            for (int rr = 0; rr < 2; rr++) {
                int gm = gm0 + rr * 8;
                if (gm >= M) continue;
                float v0 = d[rr * 2 + 0], v1 = d[rr * 2 + 1];
                if (BIAS_MODE == 1) { v0 += bc0; v1 += bc1; }
                else { float br = bptr[gm]; v0 += br; v1 += br; }
                long idx = (long)gm * ldc + gn;
                if (EPI == 1) {
                    __half h0 = __float2half_rn(v0), h1 = __float2half_rn(v1);
                    *reinterpret_cast<uint32_t*>(Ch + idx) =
                        (uint32_t)__half_as_ushort(h0) | ((uint32_t)__half_as_ushort(h1) << 16);
                } else {
                    *reinterpret_cast<float2*>(Cm + idx) = make_float2(v0, v1);
                }
                if (EPI == 3) {
                    gs[mf][rr]  += v0 + v1;
                    gs2[mf][rr] += v0 * v0 + v1 * v1;
                }
            }
        }
    }

    if (EPI == 3) {
#pragma unroll
        for (int mf = 0; mf < 2; mf++)
#pragma unroll
            for (int rr = 0; rr < 2; rr++) {
#pragma unroll
                for (int o = 16; o; o >>= 1) {
                    gs[mf][rr]  += __shfl_xor_sync(0xffffffffu, gs[mf][rr],  o);
                    gs2[mf][rr] += __shfl_xor_sync(0xffffffffu, gs2[mf][rr], o);
                }
                if (lane == 0) {
                    int gidx = (m0 + wm * 32 + mf * 16 + rr * 8) >> 3;   // 0..31
                    atomicAdd(aux + (z1 * 32 + gidx) * 2 + 0, gs[mf][rr]);
                    atomicAdd(aux + (z1 * 32 + gidx) * 2 + 1, gs2[mf][rr]);
                }
            }
    }
}

// ---------------- prep: convert weights + zero accumulators ------------------
__global__ void prep_kernel(const float* __restrict__ ef_w,
                            const float* __restrict__ hm1_w,
                            const float* __restrict__ merge_w,
                            __half* __restrict__ w_h,
                            __half* __restrict__ mw_h,
                            float* __restrict__ hacc, float* __restrict__ stat2)
{
    int i = blockIdx.x * 256 + threadIdx.x;
    if (i < DEXP * C_)    w_h[WOFF_EF + i]  = __float2half_rn(ef_w[i]);
    if (i < P_ * C_ * C_) w_h[WOFF_HM1 + i] = __float2half_rn(hm1_w[i]);
    if (i < C_ * DEXP)    mw_h[i] = __float2half_rn(merge_w[i]);
    if (i < B_ * P_ * HW_) hacc[i] = 0.f;
    if (i < B_ * 32 * 2)   stat2[i] = 0.f;
}

// -------- transpose x (B,C,HW) -> fp16 plane (B,HW,C), uint2 stores ----------
__global__ void split_x_kernel(const float* __restrict__ x, __half* __restrict__ xh)
{
    __shared__ float tile[32][33];
    int b = blockIdx.z;
    int hw0 = blockIdx.x * 32, c0 = blockIdx.y * 32;
    const float* xb = x + (long)b * C_ * HW_;
    int tx = threadIdx.x, ty = threadIdx.y;   // 32 x 8
#pragma unroll
    for (int i = 0; i < 32; i += 8) {
        int c = c0 + ty + i, hw = hw0 + tx;
        tile[ty + i][tx] = (hw < HW_) ? xb[(long)c * HW_ + hw] : 0.f;
    }
    __syncthreads();
    int tid = ty * 32 + tx;
    int cq   = tid & 7;            // 8 c-quads (4 channels each)
    int hwl0 = tid >> 3;           // 0..31
    {
        int hwl = hwl0;
        int hw = hw0 + hwl;
        if (hw < HW_) {
            __half h0 = __float2half_rn(tile[4 * cq + 0][hwl]);
            __half h1 = __float2half_rn(tile[4 * cq + 1][hwl]);
            __half h2 = __float2half_rn(tile[4 * cq + 2][hwl]);
            __half h3 = __float2half_rn(tile[4 * cq + 3][hwl]);
            long idx = (long)b * HW_ * C_ + (long)hw * C_ + c0 + 4 * cq;
            uint2 v;
            v.x = (uint32_t)__half_as_ushort(h0) | ((uint32_t)__half_as_ushort(h1) << 16);
            v.y = (uint32_t)__half_as_ushort(h2) | ((uint32_t)__half_as_ushort(h3) << 16);
            *reinterpret_cast<uint2*>(xh + idx) = v;
        }
    }
}

__global__ void heat_exp_kernel(const float* __restrict__ hacc,
                                const float* __restrict__ hm2_b,
                                float* __restrict__ heat)
{
    int i = blockIdx.x * 256 + threadIdx.x;
    if (i >= B_ * P_ * HW_) return;
    int p = (i / HW_) % P_;
    heat[i] = expf(hacc[i] + hm2_b[p]);
}

// --------- deformable bilinear gather: fp16 source, hoisted offsets ----------
__global__ void sample_kernel(const __half* __restrict__ efs,  // (B, HW, 512) fp16
                              const float* __restrict__ heat,  // (B*P, HW)
                              const float* __restrict__ offs,  // (B, P*KB*2, HW)
                              __half* __restrict__ oh)         // fp16 out (B,HW,512)
{
    int gw = (blockIdx.x * blockDim.x + threadIdx.x) >> 5;
    int lane = threadIdx.x & 31;
    if (gw >= B_ * P_ * HW_) return;
    int i  = gw % HW_;
    int bp = gw / HW_;
    int p  = bp % P_;
    int b  = bp / P_;
    int y = i / W_, x = i % W_;

    const uint4* efb = reinterpret_cast<const uint4*>(
        efs + ((long)b * HW_) * DEXP + p * C_ + lane * 8);
    const float* heatb = heat + (long)bp * HW_;
    const float* offb  = offs + ((long)b * (P_ * KB_ * 2) + p * KB_ * 2) * HW_;

    // hoist all 10 offset loads -> all tap addresses computable up front (MLP)
    float ys[KB_], xs[KB_];
#pragma unroll
    for (int k = 0; k < KB_; k++) {
        ys[k] = (float)y + offb[(k * 2 + 0) * HW_ + i];
        xs[k] = (float)x + offb[(k * 2 + 1) * HW_ + i];
    }

    float n[8];
#pragma unroll
    for (int j = 0; j < 8; j++) n[j] = 0.f;
    float den = 0.f;

#pragma unroll
    for (int k = 0; k < KB_; k++) {
        float y0f = floorf(ys[k]), x0f = floorf(xs[k]);
#pragma unroll
        for (int c4 = 0; c4 < 4; c4++) {
            float yi = y0f + (float)(c4 >> 1);
            float xi = x0f + (float)(c4 & 1);
            if (yi < 0.f || yi > (float)(H_ - 1) || xi < 0.f || xi > (float)(W_ - 1))
                continue;
            float w = (1.f - fabsf(ys[k] - yi)) * (1.f - fabsf(xs[k] - xi));
            int src = (int)yi * W_ + (int)xi;
            float wh = w * heatb[src];
            den += wh;
            uint4 u = efb[(long)src * (DEXP / 8)];
            float2 f0 = __half22float2(*reinterpret_cast<__half2*>(&u.x));
            float2 f1 = __half22float2(*reinterpret_cast<__half2*>(&u.y));
            float2 f2 = __half22float2(*reinterpret_cast<__half2*>(&u.z));
            float2 f3 = __half22float2(*reinterpret_cast<__half2*>(&u.w));
            n[0] += wh * f0.x; n[1] += wh * f0.y;
            n[2] += wh * f1.x; n[3] += wh * f1.y;
            n[4] += wh * f2.x; n[5] += wh * f2.y;
            n[6] += wh * f3.x; n[7] += wh * f3.y;
        }
    }
    float inv = 1.f / (den + 1e-6f);
    unsigned short hh[8];
#pragma unroll
    for (int j = 0; j < 8; j++) hh[j] = __half_as_ushort(__float2half_rn(n[j] * inv));
    uint4 ph;
    ph.x = (uint32_t)hh[0] | ((uint32_t)hh[1] << 16);
    ph.y = (uint32_t)hh[2] | ((uint32_t)hh[3] << 16);
    ph.z = (uint32_t)hh[4] | ((uint32_t)hh[5] << 16);
    ph.w = (uint32_t)hh[6] | ((uint32_t)hh[7] << 16);
    long obase = ((long)b * HW_ + i) * DEXP + p * C_ + lane * 8;
    *reinterpret_cast<uint4*>(oh + obase) = ph;
}

// ---------------- GroupNorm finalize (float4, stats precomputed) -------------
__global__ void gn_norm(const float* __restrict__ merged,
                        const float* __restrict__ stat2,
                        const float* __restrict__ gn_g,
                        const float* __restrict__ gn_b,
                        float* __restrict__ out)
{
    long i4 = (long)blockIdx.x * 256 + threadIdx.x;
    const long total4 = (long)B_ * C_ * HW_ / 4;
    if (i4 >= total4) return;
    long idx = i4 * 4;
    int c = (int)((idx / HW_) % C_);
    int b = (int)(idx / ((long)C_ * HW_));
    int g = c >> 3;
    const float n = 8.f * HW_;
    float s  = stat2[(b * 32 + g) * 2 + 0];
    float s2 = stat2[(b * 32 + g) * 2 + 1];
    float mu   = s / n;
    float var  = s2 / n - mu * mu;
    float rstd = rsqrtf(var + 1e-5f);
    float sc = rstd * gn_g[c];
    float sh = gn_b[c] - mu * sc;
    float4 v = *reinterpret_cast<const float4*>(merged + idx);
    float4 r;
    r.x = fmaxf(v.x * sc + sh, 0.f);
    r.y = fmaxf(v.y * sc + sh, 0.f);
    r.z = fmaxf(v.z * sc + sh, 0.f);
    r.w = fmaxf(v.w * sc + sh, 0.f);
    *reinterpret_cast<float4*>(out + idx) = r;
}

// ---------------- launch ------------------------------------------------------
extern "C" void kernel_launch(void* const* d_in, const int* in_sizes, int n_in,
                              void* d_out, int out_size)
{
    const float* x       = (const float*)d_in[0];
    const float* offsets = (const float*)d_in[1];
    const float* ef_w    = (const float*)d_in[2];
    const float* ef_b    = (const float*)d_in[3];
    const float* hm1_w   = (const float*)d_in[4];
    const float* hm1_b   = (const float*)d_in[5];
    const float* hm2_w   = (const float*)d_in[6];
    const float* hm2_b   = (const float*)d_in[7];
    const float* merge_w = (const float*)d_in[8];
    const float* merge_b = (const float*)d_in[9];
    const float* gn_g    = (const float*)d_in[10];
    const float* gn_b    = (const float*)d_in[11];
    float* out = (float*)d_out;

    float *heat, *hacc, *merged, *stat2;
    __half *efs_h, *out_h, *xs_h, *w_h, *mw_h;
    cudaGetSymbolAddress((void**)&efs_h,  g_efs_h);
    cudaGetSymbolAddress((void**)&out_h,  g_out_h);
    cudaGetSymbolAddress((void**)&xs_h,   g_xs_h);
    cudaGetSymbolAddress((void**)&w_h,    g_w_h);
    cudaGetSymbolAddress((void**)&mw_h,   g_mw_h);
    cudaGetSymbolAddress((void**)&heat,   g_heat);
    cudaGetSymbolAddress((void**)&hacc,   g_hacc);
    cudaGetSymbolAddress((void**)&merged, g_merged);
    cudaGetSymbolAddress((void**)&stat2,  g_stat2);

    cudaFuncSetAttribute(tc_gemm<1, 1>, cudaFuncAttributeMaxDynamicSharedMemorySize, GEMM_SMEM);
    cudaFuncSetAttribute(tc_gemm<1, 2>, cudaFuncAttributeMaxDynamicSharedMemorySize, GEMM_SMEM);
    cudaFuncSetAttribute(tc_gemm<2, 3>, cudaFuncAttributeMaxDynamicSharedMemorySize, GEMM_SMEM);

    // 0) prep: weight conversion + zeroing; x transpose->fp16
    prep_kernel<<<(DEXP * C_ + 255) / 256, 256>>>(ef_w, hm1_w, merge_w,
                                                  w_h, mw_h, hacc, stat2);
    {
        dim3 grid((HW_ + 31) / 32, C_ / 32, B_);
        split_x_kernel<<<grid, dim3(32, 8)>>>(x, xs_h);
    }

    // 1) GEMM1: efs[b][i][d] = fp16( sum_c xT[b][i][c]*ef_w[d][c] + ef_b[d] )
    {
        dim3 grid(DEXP / GBN, (HW_ + GBM - 1) / GBM, B_);
        tc_gemm<1, 1><<<grid, 256, GEMM_SMEM>>>(
            xs_h, C_, (long)HW_ * C_, 0,
            w_h + WOFF_EF, C_, 0, 0,
            nullptr, DEXP, (long)HW_ * DEXP, 0,
            ef_b, 0, 0,
            efs_h, nullptr, nullptr,
            1, HW_, DEXP, C_);
    }

    // 2) GEMM2 + heat fusion
    {
        dim3 grid(C_ / GBN, (HW_ + GBM - 1) / GBM, B_ * P_);
        tc_gemm<1, 2><<<grid, 256, GEMM_SMEM>>>(
            efs_h, DEXP, (long)HW_ * DEXP, (long)C_,
            w_h + WOFF_HM1, C_, 0, (long)C_ * C_,
            nullptr, 0, 0, 0,
            hm1_b, 0, (long)C_,
            nullptr, hm2_w, hacc,
            P_, HW_, C_, C_);
    }

    // 3) heat = exp(hacc + hm2_b)
    heat_exp_kernel<<<(B_ * P_ * HW_ + 255) / 256, 256>>>(hacc, hm2_b, heat);

    // 4) gather (fp16 source) -> fp16 outs
    {
        int warps = B_ * P_ * HW_;
        sample_kernel<<<(warps * 32 + 255) / 256, 256>>>(efs_h, heat, offsets, out_h);
    }

    // 5) GEMM3 + GN stats
    {
        dim3 grid((HW_ + GBN - 1) / GBN, C_ / GBM, B_);
        tc_gemm<2, 3><<<grid, 256, GEMM_SMEM>>>(
            mw_h, DEXP, 0, 0,
            out_h, DEXP, (long)HW_ * DEXP, 0,
            merged, HW_, (long)C_ * HW_, 0,
            merge_b, 0, 0,
            nullptr, nullptr, stat2,
            1, C_, HW_, DEXP);
    }

    // 6) GroupNorm finalize + ReLU
    {
        long total4 = (long)B_ * C_ * HW_ / 4;
        gn_norm<<<(int)((total4 + 255) / 256), 256>>>(merged, stat2, gn_g, gn_b, out);
    }
}

// round 14
// speedup vs baseline: 1.1991x; 1.0401x over previous
#include <cuda_runtime.h>
#include <cuda_fp16.h>
#include <cstdint>
#include <math.h>

#define B_   2
#define C_   256
#define H_   100
#define W_   152
#define HW_  (H_*W_)
#define P_   2
#define KB_  5          // bins
#define DEXP (P_*C_)    // 512

// ---------------- scratch (static device memory; no allocation) -------------
__device__ __half   g_efs_h[(size_t)B_*HW_*DEXP];   // ef fp16 (GEMM2 A + gather src)
__device__ __half   g_out_h[(size_t)B_*HW_*DEXP];   // gather out fp16 (GEMM3 B)
__device__ __half   g_xs_h [(size_t)B_*HW_*C_];     // x transposed fp16 (GEMM1 A)
#define WOFF_EF   0
#define WOFF_HM1  (DEXP*C_)                  // 131072
__device__ __half   g_w_h  [DEXP*C_ + P_*C_*C_];    // ef_w, hm1_w fp16 (B operands)
__device__ __half   g_mw_h [C_*DEXP];               // merge_w fp16 (GEMM3 A)
__device__ float g_heat [B_*P_*HW_];
__device__ float g_hacc [B_*P_*HW_];
__device__ float g_merged[(size_t)B_*C_*HW_];
__device__ float g_stat2[B_*32*2];           // (b,g) -> sum, sumsq (atomic)

// ======================= helpers =============================================
__device__ __forceinline__ uint32_t smem_u32(const void* p) {
    uint32_t a;
    asm("{ .reg .u64 t; cvta.to.shared.u64 t, %1; cvt.u32.u64 %0, t; }" : "=r"(a) : "l"(p));
    return a;
}
__device__ __forceinline__ void ldsm_x4(uint32_t* r, uint32_t a) {
    asm volatile("ldmatrix.sync.aligned.m8n8.x4.shared.b16 {%0,%1,%2,%3}, [%4];"
        : "=r"(r[0]), "=r"(r[1]), "=r"(r[2]), "=r"(r[3]) : "r"(a));
}
__device__ __forceinline__ void mma_f16(float* d, const uint32_t* a, const uint32_t* b) {
    asm volatile("mma.sync.aligned.m16n8k16.row.col.f32.f16.f16.f32 "
        "{%0,%1,%2,%3}, {%4,%5,%6,%7}, {%8,%9}, {%0,%1,%2,%3};"
        : "+f"(d[0]), "+f"(d[1]), "+f"(d[2]), "+f"(d[3])
        : "r"(a[0]), "r"(a[1]), "r"(a[2]), "r"(a[3]), "r"(b[0]), "r"(b[1]));
}
__device__ __forceinline__ void cp_async16(uint32_t dst, const void* src, int src_bytes) {
    asm volatile("cp.async.cg.shared.global [%0], [%1], 16, %2;"
        :: "r"(dst), "l"(src), "r"(src_bytes) : "memory");
}
#define CP_COMMIT() asm volatile("cp.async.commit_group;" ::: "memory")
#define CP_WAIT(n)  asm volatile("cp.async.wait_group %0;" :: "n"(n) : "memory")

// ================= single-pass fp16 mma.sync GEMM ============================
// D[M,N] = A[M,K] * B[N,K]^T;  A, B plain fp16 planes, K-major.
// 128x128 CTA tile, warp tile 32x64 (4 M-warps x 2 N-warps), 2 CTAs/SM.
// GBK=64: double-length K-tiles halve per-iteration loop overhead.
// 2-stage cp.async ring, prefetch distance 1, one __syncthreads per K-tile.
// EPI: 0/3 = fp32 C (+bias); 3 adds atomic GN sums (GEMM3);
//      1 = fp16 C plane ONLY (GEMM1);
//      2 = no C store; heat fusion: atomicAdd( sum_n relu(c+bias)*w2[n] ).
#define GBM 128
#define GBN 128
#define GBK 64
#define ROWB   144                 // 64 halfs + 16B pad; 36-word stride -> LDSM conflict-free
#define ATILE_B (128*ROWB)         // 18432
#define BTILE_B (128*ROWB)         // 18432
#define BUF_B  (ATILE_B + BTILE_B) // 36864
#define NSTAGE 2
#define GEMM_SMEM (NSTAGE*BUF_B)   // 73728 B

template<int BIAS_MODE, int EPI>
__global__ __launch_bounds__(256, 2)
void tc_gemm(const __half* __restrict__ Ahp, int lda, long sA1, long sA2,
             const __half* __restrict__ Bhp, int ldb, long sB1, long sB2,
             float* __restrict__ Cm, int ldc, long sC1, long sC2,
             const float* __restrict__ bias, long sb1, long sb2,
             __half* __restrict__ Ch,
             const float* __restrict__ w2, float* __restrict__ aux,
             int zdiv, int M, int N, int K)
{
    extern __shared__ char smem[];
    const uint32_t sbase = smem_u32(smem);
    const int tid = threadIdx.x;
    const int lane = tid & 31, wid = tid >> 5;

    const int z = blockIdx.z;
    const int z1 = z / zdiv, z2 = z % zdiv;
    Ahp += z1 * sA1 + z2 * sA2;
    Bhp += z1 * sB1 + z2 * sB2;
    const float* bptr = bias + z1 * sb1 + z2 * sb2;

    const int m0 = blockIdx.y * GBM;
    const int n0 = blockIdx.x * GBN;

    const int wm = wid & 3;          // 4 warps over M (32 rows each)
    const int wn = wid >> 2;         // 2 warps over N (64 cols each)
    const int lane8 = lane & 7, sel = lane >> 3;

    float acc[2][8][4];
#pragma unroll
    for (int i = 0; i < 2; i++)
#pragma unroll
        for (int j = 0; j < 8; j++)
#pragma unroll
            for (int q = 0; q < 4; q++) acc[i][j][q] = 0.f;

    const int nk = K / GBK;

    auto LOADCP = [&](int kt, int stage) {
        const int k0 = kt * GBK;
        const uint32_t sb = sbase + stage * BUF_B;
#pragma unroll
        for (int j = 0; j < 4; j++) {
            int idx = tid + j * 256;           // 0..1023
            int row = idx >> 3, q = idx & 7;   // 8 quads of 16B per 64-K row
            uint32_t off = (uint32_t)(row * ROWB + q * 16);
            int gm = m0 + row, gn = n0 + row;
            int szA = (gm < M) ? 16 : 0;
            int szB = (gn < N) ? 16 : 0;
            long ga = (long)(gm < M ? gm : M - 1) * lda + k0 + q * 8;
            long gb = (long)(gn < N ? gn : N - 1) * ldb + k0 + q * 8;
            cp_async16(sb + off,           Ahp + ga, szA);
            cp_async16(sb + ATILE_B + off, Bhp + gb, szB);
        }
    };

    auto COMPUTE = [&](int stage) {
        const uint32_t ah_b = sbase + stage * BUF_B;
        const uint32_t bh_b = ah_b + ATILE_B;
#pragma unroll
        for (int ks = 0; ks < 4; ks++) {
            const int kb = ks * 16;
            uint32_t ah[2][4];
#pragma unroll
            for (int mf = 0; mf < 2; mf++) {
                int row = wm * 32 + mf * 16 + lane8 + (sel & 1) * 8;
                int kc  = kb + (sel & 2) * 4;
                ldsm_x4(ah[mf], ah_b + (uint32_t)(row * ROWB + kc * 2));
            }
#pragma unroll
            for (int nf2 = 0; nf2 < 4; nf2++) {
                int nrow = wn * 64 + nf2 * 16 + lane8 + (sel & 2) * 4;
                int kc   = kb + (sel & 1) * 8;
                uint32_t bh4[4];
                ldsm_x4(bh4, bh_b + (uint32_t)(nrow * ROWB + kc * 2));
#pragma unroll
                for (int half = 0; half < 2; half++)
#pragma unroll
                    for (int mf = 0; mf < 2; mf++)
                        mma_f16(acc[mf][nf2 * 2 + half], ah[mf], bh4 + half * 2);
            }
        }
    };

    // 2-stage pipeline, prefetch distance 1, one barrier per K-tile
    LOADCP(0, 0); CP_COMMIT();
    for (int kt = 0; kt < nk; kt++) {
        CP_WAIT(0);
        __syncthreads();
        if (kt + 1 < nk) { LOADCP(kt + 1, (kt + 1) & 1); CP_COMMIT(); }
        COMPUTE(kt & 1);
    }

    // ---- epilogue ----
    const int g = lane >> 2, t = lane & 3;

    if (EPI == 2) {
        const float* w2p = w2 + z2 * C_;
        float s[2][2] = {{0.f, 0.f}, {0.f, 0.f}};
#pragma unroll
        for (int nf = 0; nf < 8; nf++) {
            int gn = n0 + wn * 64 + nf * 8 + 2 * t;
            float b0 = bptr[gn], b1 = bptr[gn + 1];
            float w0 = w2p[gn],  w1 = w2p[gn + 1];
#pragma unroll
            for (int mf = 0; mf < 2; mf++)
#pragma unroll
                for (int rr = 0; rr < 2; rr++) {
                    float v0 = fmaxf(acc[mf][nf][rr * 2 + 0] + b0, 0.f);
                    float v1 = fmaxf(acc[mf][nf][rr * 2 + 1] + b1, 0.f);
                    s[mf][rr] += v0 * w0 + v1 * w1;
                }
        }
#pragma unroll
        for (int mf = 0; mf < 2; mf++)
#pragma unroll
            for (int rr = 0; rr < 2; rr++) {
                s[mf][rr] += __shfl_xor_sync(0xffffffffu, s[mf][rr], 1);
                s[mf][rr] += __shfl_xor_sync(0xffffffffu, s[mf][rr], 2);
            }
        if (t == 0) {
            float* hz = aux + (long)z * HW_;
#pragma unroll
            for (int mf = 0; mf < 2; mf++)
#pragma unroll
                for (int rr = 0; rr < 2; rr++) {
                    int gm = m0 + wm * 32 + mf * 16 + rr * 8 + g;
                    if (gm < M) atomicAdd(hz + gm, s[mf][rr]);
                }
        }
        return;
    }

    if (EPI != 1) Cm += z1 * sC1 + z2 * sC2;
    if (EPI == 1) Ch += z1 * sC1 + z2 * sC2;

    float gs[2][2]  = {{0.f, 0.f}, {0.f, 0.f}};
    float gs2[2][2] = {{0.f, 0.f}, {0.f, 0.f}};

#pragma unroll
    for (int mf = 0; mf < 2; mf++) {
#pragma unroll
        for (int nf = 0; nf < 8; nf++) {
            const float* d = acc[mf][nf];
            int gm0 = m0 + wm * 32 + mf * 16 + g;
            int gn  = n0 + wn * 64 + nf * 8 + 2 * t;
            if (gn >= N) continue;
            float bc0 = 0.f, bc1 = 0.f;
            if (BIAS_MODE == 1) { bc0 = bptr[gn]; bc1 = bptr[gn + 1]; }
#pragma unroll
            for (int rr = 0; rr < 2; rr++) {
                int gm = gm0 + rr * 8;
                if (gm >= M) continue;
                float v0 = d[rr * 2 + 0], v1 = d[rr * 2 + 1];
                if (BIAS_MODE == 1) { v0 += bc0; v1 += bc1; }
                else { float br = bptr[gm]; v0 += br; v1 += br; }
                long idx = (long)gm * ldc + gn;
                if (EPI == 1) {
                    __half h0 = __float2half_rn(v0), h1 = __float2half_rn(v1);
                    *reinterpret_cast<uint32_t*>(Ch + idx) =
                        (uint32_t)__half_as_ushort(h0) | ((uint32_t)__half_as_ushort(h1) << 16);
                } else {
                    *reinterpret_cast<float2*>(Cm + idx) = make_float2(v0, v1);
                }
                if (EPI == 3) {
                    gs[mf][rr]  += v0 + v1;
                    gs2[mf][rr] += v0 * v0 + v1 * v1;
                }
            }
        }
    }

    if (EPI == 3) {
#pragma unroll
        for (int mf = 0; mf < 2; mf++)
#pragma unroll
            for (int rr = 0; rr < 2; rr++) {
#pragma unroll
                for (int o = 16; o; o >>= 1) {
                    gs[mf][rr]  += __shfl_xor_sync(0xffffffffu, gs[mf][rr],  o);
                    gs2[mf][rr] += __shfl_xor_sync(0xffffffffu, gs2[mf][rr], o);
                }
                if (lane == 0) {
                    int gidx = (m0 + wm * 32 + mf * 16 + rr * 8) >> 3;   // 0..31
                    atomicAdd(aux + (z1 * 32 + gidx) * 2 + 0, gs[mf][rr]);
                    atomicAdd(aux + (z1 * 32 + gidx) * 2 + 1, gs2[mf][rr]);
                }
            }
    }
}

// ---------------- prep: convert weights + zero accumulators ------------------
__global__ void prep_kernel(const float* __restrict__ ef_w,
                            const float* __restrict__ hm1_w,
                            const float* __restrict__ merge_w,
                            __half* __restrict__ w_h,
                            __half* __restrict__ mw_h,
                            float* __restrict__ hacc, float* __restrict__ stat2)
{
    int i = blockIdx.x * 256 + threadIdx.x;
    if (i < DEXP * C_)    w_h[WOFF_EF + i]  = __float2half_rn(ef_w[i]);
    if (i < P_ * C_ * C_) w_h[WOFF_HM1 + i] = __float2half_rn(hm1_w[i]);
    if (i < C_ * DEXP)    mw_h[i] = __float2half_rn(merge_w[i]);
    if (i < B_ * P_ * HW_) hacc[i] = 0.f;
    if (i < B_ * 32 * 2)   stat2[i] = 0.f;
}

// -------- transpose x (B,C,HW) -> fp16 plane (B,HW,C), uint2 stores ----------
__global__ void split_x_kernel(const float* __restrict__ x, __half* __restrict__ xh)
{
    __shared__ float tile[32][33];
    int b = blockIdx.z;
    int hw0 = blockIdx.x * 32, c0 = blockIdx.y * 32;
    const float* xb = x + (long)b * C_ * HW_;
    int tx = threadIdx.x, ty = threadIdx.y;   // 32 x 8
#pragma unroll
    for (int i = 0; i < 32; i += 8) {
        int c = c0 + ty + i, hw = hw0 + tx;
        tile[ty + i][tx] = (hw < HW_) ? xb[(long)c * HW_ + hw] : 0.f;
    }
    __syncthreads();
    int tid = ty * 32 + tx;
    int cq   = tid & 7;            // 8 c-quads (4 channels each)
    int hwl0 = tid >> 3;           // 0..31
    {
        int hwl = hwl0;
        int hw = hw0 + hwl;
        if (hw < HW_) {
            __half h0 = __float2half_rn(tile[4 * cq + 0][hwl]);
            __half h1 = __float2half_rn(tile[4 * cq + 1][hwl]);
            __half h2 = __float2half_rn(tile[4 * cq + 2][hwl]);
            __half h3 = __float2half_rn(tile[4 * cq + 3][hwl]);
            long idx = (long)b * HW_ * C_ + (long)hw * C_ + c0 + 4 * cq;
            uint2 v;
            v.x = (uint32_t)__half_as_ushort(h0) | ((uint32_t)__half_as_ushort(h1) << 16);
            v.y = (uint32_t)__half_as_ushort(h2) | ((uint32_t)__half_as_ushort(h3) << 16);
            *reinterpret_cast<uint2*>(xh + idx) = v;
        }
    }
}

__global__ void heat_exp_kernel(const float* __restrict__ hacc,
                                const float* __restrict__ hm2_b,
                                float* __restrict__ heat)
{
    int i = blockIdx.x * 256 + threadIdx.x;
    if (i >= B_ * P_ * HW_) return;
    int p = (i / HW_) % P_;
    heat[i] = expf(hacc[i] + hm2_b[p]);
}

// --------- deformable bilinear gather: fp16 source ---------------------------
__global__ void sample_kernel(const __half* __restrict__ efs,  // (B, HW, 512) fp16
                              const float* __restrict__ heat,  // (B*P, HW)
                              const float* __restrict__ offs,  // (B, P*KB*2, HW)
                              __half* __restrict__ oh)         // fp16 out (B,HW,512)
{
    int gw = (blockIdx.x * blockDim.x + threadIdx.x) >> 5;
    int lane = threadIdx.x & 31;
    if (gw >= B_ * P_ * HW_) return;
    int i  = gw % HW_;
    int bp = gw / HW_;
    int p  = bp % P_;
    int b  = bp / P_;
    int y = i / W_, x = i % W_;

    const uint4* efb = reinterpret_cast<const uint4*>(
        efs + ((long)b * HW_) * DEXP + p * C_ + lane * 8);
    const float* heatb = heat + (long)bp * HW_;
    const float* offb  = offs + ((long)b * (P_ * KB_ * 2) + p * KB_ * 2) * HW_;

    float ys[KB_], xs[KB_];
#pragma unroll
    for (int k = 0; k < KB_; k++) {
        ys[k] = (float)y + offb[(k * 2 + 0) * HW_ + i];
        xs[k] = (float)x + offb[(k * 2 + 1) * HW_ + i];
    }

    float n[8];
#pragma unroll
    for (int j = 0; j < 8; j++) n[j] = 0.f;
    float den = 0.f;

#pragma unroll
    for (int k = 0; k < KB_; k++) {
        float y0f = floorf(ys[k]), x0f = floorf(xs[k]);
#pragma unroll
        for (int c4 = 0; c4 < 4; c4++) {
            float yi = y0f + (float)(c4 >> 1);
            float xi = x0f + (float)(c4 & 1);
            if (yi < 0.f || yi > (float)(H_ - 1) || xi < 0.f || xi > (float)(W_ - 1))
                continue;
            float w = (1.f - fabsf(ys[k] - yi)) * (1.f - fabsf(xs[k] - xi));
            int src = (int)yi * W_ + (int)xi;
            float wh = w * heatb[src];
            den += wh;
            uint4 u = efb[(long)src * (DEXP / 8)];
            float2 f0 = __half22float2(*reinterpret_cast<__half2*>(&u.x));
            float2 f1 = __half22float2(*reinterpret_cast<__half2*>(&u.y));
            float2 f2 = __half22float2(*reinterpret_cast<__half2*>(&u.z));
            float2 f3 = __half22float2(*reinterpret_cast<__half2*>(&u.w));
            n[0] += wh * f0.x; n[1] += wh * f0.y;
            n[2] += wh * f1.x; n[3] += wh * f1.y;
            n[4] += wh * f2.x; n[5] += wh * f2.y;
            n[6] += wh * f3.x; n[7] += wh * f3.y;
        }
    }
    float inv = 1.f / (den + 1e-6f);
    unsigned short hh[8];
#pragma unroll
    for (int j = 0; j < 8; j++) hh[j] = __half_as_ushort(__float2half_rn(n[j] * inv));
    uint4 ph;
    ph.x = (uint32_t)hh[0] | ((uint32_t)hh[1] << 16);
    ph.y = (uint32_t)hh[2] | ((uint32_t)hh[3] << 16);
    ph.z = (uint32_t)hh[4] | ((uint32_t)hh[5] << 16);
    ph.w = (uint32_t)hh[6] | ((uint32_t)hh[7] << 16);
    long obase = ((long)b * HW_ + i) * DEXP + p * C_ + lane * 8;
    *reinterpret_cast<uint4*>(oh + obase) = ph;
}

// ---------------- GroupNorm finalize (float4, stats precomputed) -------------
__global__ void gn_norm(const float* __restrict__ merged,
                        const float* __restrict__ stat2,
                        const float* __restrict__ gn_g,
                        const float* __restrict__ gn_b,
                        float* __restrict__ out)
{
    long i4 = (long)blockIdx.x * 256 + threadIdx.x;
    const long total4 = (long)B_ * C_ * HW_ / 4;
    if (i4 >= total4) return;
    long idx = i4 * 4;
    int c = (int)((idx / HW_) % C_);
    int b = (int)(idx / ((long)C_ * HW_));
    int g = c >> 3;
    const float n = 8.f * HW_;
    float s  = stat2[(b * 32 + g) * 2 + 0];
    float s2 = stat2[(b * 32 + g) * 2 + 1];
    float mu   = s / n;
    float var  = s2 / n - mu * mu;
    float rstd = rsqrtf(var + 1e-5f);
    float sc = rstd * gn_g[c];
    float sh = gn_b[c] - mu * sc;
    float4 v = *reinterpret_cast<const float4*>(merged + idx);
    float4 r;
    r.x = fmaxf(v.x * sc + sh, 0.f);
    r.y = fmaxf(v.y * sc + sh, 0.f);
    r.z = fmaxf(v.z * sc + sh, 0.f);
    r.w = fmaxf(v.w * sc + sh, 0.f);
    *reinterpret_cast<float4*>(out + idx) = r;
}

// ---------------- launch ------------------------------------------------------
extern "C" void kernel_launch(void* const* d_in, const int* in_sizes, int n_in,
                              void* d_out, int out_size)
{
    const float* x       = (const float*)d_in[0];
    const float* offsets = (const float*)d_in[1];
    const float* ef_w    = (const float*)d_in[2];
    const float* ef_b    = (const float*)d_in[3];
    const float* hm1_w   = (const float*)d_in[4];
    const float* hm1_b   = (const float*)d_in[5];
    const float* hm2_w   = (const float*)d_in[6];
    const float* hm2_b   = (const float*)d_in[7];
    const float* merge_w = (const float*)d_in[8];
    const float* merge_b = (const float*)d_in[9];
    const float* gn_g    = (const float*)d_in[10];
    const float* gn_b    = (const float*)d_in[11];
    float* out = (float*)d_out;

    float *heat, *hacc, *merged, *stat2;
    __half *efs_h, *out_h, *xs_h, *w_h, *mw_h;
    cudaGetSymbolAddress((void**)&efs_h,  g_efs_h);
    cudaGetSymbolAddress((void**)&out_h,  g_out_h);
    cudaGetSymbolAddress((void**)&xs_h,   g_xs_h);
    cudaGetSymbolAddress((void**)&w_h,    g_w_h);
    cudaGetSymbolAddress((void**)&mw_h,   g_mw_h);
    cudaGetSymbolAddress((void**)&heat,   g_heat);
    cudaGetSymbolAddress((void**)&hacc,   g_hacc);
    cudaGetSymbolAddress((void**)&merged, g_merged);
    cudaGetSymbolAddress((void**)&stat2,  g_stat2);

    cudaFuncSetAttribute(tc_gemm<1, 1>, cudaFuncAttributeMaxDynamicSharedMemorySize, GEMM_SMEM);
    cudaFuncSetAttribute(tc_gemm<1, 2>, cudaFuncAttributeMaxDynamicSharedMemorySize, GEMM_SMEM);
    cudaFuncSetAttribute(tc_gemm<2, 3>, cudaFuncAttributeMaxDynamicSharedMemorySize, GEMM_SMEM);

    // 0) prep: weight conversion + zeroing; x transpose->fp16
    prep_kernel<<<(DEXP * C_ + 255) / 256, 256>>>(ef_w, hm1_w, merge_w,
                                                  w_h, mw_h, hacc, stat2);
    {
        dim3 grid((HW_ + 31) / 32, C_ / 32, B_);
        split_x_kernel<<<grid, dim3(32, 8)>>>(x, xs_h);
    }

    // 1) GEMM1: efs[b][i][d] = fp16( sum_c xT[b][i][c]*ef_w[d][c] + ef_b[d] )
    {
        dim3 grid(DEXP / GBN, (HW_ + GBM - 1) / GBM, B_);
        tc_gemm<1, 1><<<grid, 256, GEMM_SMEM>>>(
            xs_h, C_, (long)HW_ * C_, 0,
            w_h + WOFF_EF, C_, 0, 0,
            nullptr, DEXP, (long)HW_ * DEXP, 0,
            ef_b, 0, 0,
            efs_h, nullptr, nullptr,
            1, HW_, DEXP, C_);
    }

    // 2) GEMM2 + heat fusion
    {
        dim3 grid(C_ / GBN, (HW_ + GBM - 1) / GBM, B_ * P_);
        tc_gemm<1, 2><<<grid, 256, GEMM_SMEM>>>(
            efs_h, DEXP, (long)HW_ * DEXP, (long)C_,
            w_h + WOFF_HM1, C_, 0, (long)C_ * C_,
            nullptr, 0, 0, 0,
            hm1_b, 0, (long)C_,
            nullptr, hm2_w, hacc,
            P_, HW_, C_, C_);
    }

    // 3) heat = exp(hacc + hm2_b)
    heat_exp_kernel<<<(B_ * P_ * HW_ + 255) / 256, 256>>>(hacc, hm2_b, heat);

    // 4) gather (fp16 source) -> fp16 outs
    {
        int warps = B_ * P_ * HW_;
        sample_kernel<<<(warps * 32 + 255) / 256, 256>>>(efs_h, heat, offsets, out_h);
    }

    // 5) GEMM3 + GN stats
    {
        dim3 grid((HW_ + GBN - 1) / GBN, C_ / GBM, B_);
        tc_gemm<2, 3><<<grid, 256, GEMM_SMEM>>>(
            mw_h, DEXP, 0, 0,
            out_h, DEXP, (long)HW_ * DEXP, 0,
            merged, HW_, (long)C_ * HW_, 0,
            merge_b, 0, 0,
            nullptr, nullptr, stat2,
            1, C_, HW_, DEXP);
    }

    // 6) GroupNorm finalize + ReLU
    {
        long total4 = (long)B_ * C_ * HW_ / 4;
        gn_norm<<<(int)((total4 + 255) / 256), 256>>>(merged, stat2, gn_g, gn_b, out);
    }
}

// round 15
// speedup vs baseline: 1.2021x; 1.0025x over previous
#include <cuda_runtime.h>
#include <cuda_fp16.h>
#include <cstdint>
#include <math.h>

#define B_   2
#define C_   256
#define H_   100
#define W_   152
#define HW_  (H_*W_)
#define P_   2
#define KB_  5          // bins
#define DEXP (P_*C_)    // 512

// ---------------- scratch (static device memory; no allocation) -------------
__device__ __half   g_efs_h[(size_t)B_*HW_*DEXP];   // ef fp16 (GEMM2 A + gather src)
__device__ __half   g_out_h[(size_t)B_*HW_*DEXP];   // gather out fp16 (GEMM3 B)
__device__ __half   g_xs_h [(size_t)B_*HW_*C_];     // x transposed fp16 (GEMM1 A)
#define WOFF_EF   0
#define WOFF_HM1  (DEXP*C_)                  // 131072
__device__ __half   g_w_h  [DEXP*C_ + P_*C_*C_];    // ef_w, hm1_w fp16 (B operands)
__device__ __half   g_mw_h [C_*DEXP];               // merge_w fp16 (GEMM3 A)
__device__ float  g_heat [B_*P_*HW_];
__device__ float  g_hacc [B_*P_*HW_];
__device__ __half g_merged[(size_t)B_*C_*HW_];      // merged fp16 (GN input)
__device__ float  g_stat2[B_*32*2];          // (b,g) -> sum, sumsq (atomic)

// ======================= helpers =============================================
__device__ __forceinline__ uint32_t smem_u32(const void* p) {
    uint32_t a;
    asm("{ .reg .u64 t; cvta.to.shared.u64 t, %1; cvt.u32.u64 %0, t; }" : "=r"(a) : "l"(p));
    return a;
}
__device__ __forceinline__ void ldsm_x4(uint32_t* r, uint32_t a) {
    asm volatile("ldmatrix.sync.aligned.m8n8.x4.shared.b16 {%0,%1,%2,%3}, [%4];"
        : "=r"(r[0]), "=r"(r[1]), "=r"(r[2]), "=r"(r[3]) : "r"(a));
}
__device__ __forceinline__ void mma_f16(float* d, const uint32_t* a, const uint32_t* b) {
    asm volatile("mma.sync.aligned.m16n8k16.row.col.f32.f16.f16.f32 "
        "{%0,%1,%2,%3}, {%4,%5,%6,%7}, {%8,%9}, {%0,%1,%2,%3};"
        : "+f"(d[0]), "+f"(d[1]), "+f"(d[2]), "+f"(d[3])
        : "r"(a[0]), "r"(a[1]), "r"(a[2]), "r"(a[3]), "r"(b[0]), "r"(b[1]));
}
__device__ __forceinline__ void cp_async16(uint32_t dst, const void* src, int src_bytes) {
    asm volatile("cp.async.cg.shared.global [%0], [%1], 16, %2;"
        :: "r"(dst), "l"(src), "r"(src_bytes) : "memory");
}
#define CP_COMMIT() asm volatile("cp.async.commit_group;" ::: "memory")
#define CP_WAIT(n)  asm volatile("cp.async.wait_group %0;" :: "n"(n) : "memory")

// ================= single-pass fp16 mma.sync GEMM (frozen config) ============
// D[M,N] = A[M,K] * B[N,K]^T;  A, B plain fp16 planes, K-major.
// 128x128 CTA tile, warp tile 32x64 (4 M-warps x 2 N-warps), 2 CTAs/SM.
// GBK=64, 2-stage cp.async ring, prefetch distance 1, 1 barrier per K-tile.
// EPI: 0 = fp32 C (+bias);
//      1 = fp16 C plane (GEMM1);
//      2 = no C store; heat fusion: atomicAdd( sum_n relu(c+bias)*w2[n] );
//      3 = fp16 C plane + atomic GN sums from fp32 values (GEMM3).
#define GBM 128
#define GBN 128
#define GBK 64
#define ROWB   144                 // 64 halfs + 16B pad; LDSM conflict-free
#define ATILE_B (128*ROWB)         // 18432
#define BTILE_B (128*ROWB)         // 18432
#define BUF_B  (ATILE_B + BTILE_B) // 36864
#define NSTAGE 2
#define GEMM_SMEM (NSTAGE*BUF_B)   // 73728 B

template<int BIAS_MODE, int EPI>
__global__ __launch_bounds__(256, 2)
void tc_gemm(const __half* __restrict__ Ahp, int lda, long sA1, long sA2,
             const __half* __restrict__ Bhp, int ldb, long sB1, long sB2,
             float* __restrict__ Cm, int ldc, long sC1, long sC2,
             const float* __restrict__ bias, long sb1, long sb2,
             __half* __restrict__ Ch,
             const float* __restrict__ w2, float* __restrict__ aux,
             int zdiv, int M, int N, int K)
{
    extern __shared__ char smem[];
    const uint32_t sbase = smem_u32(smem);
    const int tid = threadIdx.x;
    const int lane = tid & 31, wid = tid >> 5;

    const int z = blockIdx.z;
    const int z1 = z / zdiv, z2 = z % zdiv;
    Ahp += z1 * sA1 + z2 * sA2;
    Bhp += z1 * sB1 + z2 * sB2;
    const float* bptr = bias + z1 * sb1 + z2 * sb2;

    const int m0 = blockIdx.y * GBM;
    const int n0 = blockIdx.x * GBN;

    const int wm = wid & 3;          // 4 warps over M (32 rows each)
    const int wn = wid >> 2;         // 2 warps over N (64 cols each)
    const int lane8 = lane & 7, sel = lane >> 3;

    float acc[2][8][4];
#pragma unroll
    for (int i = 0; i < 2; i++)
#pragma unroll
        for (int j = 0; j < 8; j++)
#pragma unroll
            for (int q = 0; q < 4; q++) acc[i][j][q] = 0.f;

    const int nk = K / GBK;

    auto LOADCP = [&](int kt, int stage) {
        const int k0 = kt * GBK;
        const uint32_t sb = sbase + stage * BUF_B;
#pragma unroll
        for (int j = 0; j < 4; j++) {
            int idx = tid + j * 256;           // 0..1023
            int row = idx >> 3, q = idx & 7;   // 8 quads of 16B per 64-K row
            uint32_t off = (uint32_t)(row * ROWB + q * 16);
            int gm = m0 + row, gn = n0 + row;
            int szA = (gm < M) ? 16 : 0;
            int szB = (gn < N) ? 16 : 0;
            long ga = (long)(gm < M ? gm : M - 1) * lda + k0 + q * 8;
            long gb = (long)(gn < N ? gn : N - 1) * ldb + k0 + q * 8;
            cp_async16(sb + off,           Ahp + ga, szA);
            cp_async16(sb + ATILE_B + off, Bhp + gb, szB);
        }
    };

    auto COMPUTE = [&](int stage) {
        const uint32_t ah_b = sbase + stage * BUF_B;
        const uint32_t bh_b = ah_b + ATILE_B;
#pragma unroll
        for (int ks = 0; ks < 4; ks++) {
            const int kb = ks * 16;
            uint32_t ah[2][4];
#pragma unroll
            for (int mf = 0; mf < 2; mf++) {
                int row = wm * 32 + mf * 16 + lane8 + (sel & 1) * 8;
                int kc  = kb + (sel & 2) * 4;
                ldsm_x4(ah[mf], ah_b + (uint32_t)(row * ROWB + kc * 2));
            }
#pragma unroll
            for (int nf2 = 0; nf2 < 4; nf2++) {
                int nrow = wn * 64 + nf2 * 16 + lane8 + (sel & 2) * 4;
                int kc   = kb + (sel & 1) * 8;
                uint32_t bh4[4];
                ldsm_x4(bh4, bh_b + (uint32_t)(nrow * ROWB + kc * 2));
#pragma unroll
                for (int half = 0; half < 2; half++)
#pragma unroll
                    for (int mf = 0; mf < 2; mf++)
                        mma_f16(acc[mf][nf2 * 2 + half], ah[mf], bh4 + half * 2);
            }
        }
    };

    // 2-stage pipeline, prefetch distance 1, one barrier per K-tile
    LOADCP(0, 0); CP_COMMIT();
    for (int kt = 0; kt < nk; kt++) {
        CP_WAIT(0);
        __syncthreads();
        if (kt + 1 < nk) { LOADCP(kt + 1, (kt + 1) & 1); CP_COMMIT(); }
        COMPUTE(kt & 1);
    }

    // ---- epilogue ----
    const int g = lane >> 2, t = lane & 3;

    if (EPI == 2) {
        const float* w2p = w2 + z2 * C_;
        float s[2][2] = {{0.f, 0.f}, {0.f, 0.f}};
#pragma unroll
        for (int nf = 0; nf < 8; nf++) {
            int gn = n0 + wn * 64 + nf * 8 + 2 * t;
            float b0 = bptr[gn], b1 = bptr[gn + 1];
            float w0 = w2p[gn],  w1 = w2p[gn + 1];
#pragma unroll
            for (int mf = 0; mf < 2; mf++)
#pragma unroll
                for (int rr = 0; rr < 2; rr++) {
                    float v0 = fmaxf(acc[mf][nf][rr * 2 + 0] + b0, 0.f);
                    float v1 = fmaxf(acc[mf][nf][rr * 2 + 1] + b1, 0.f);
                    s[mf][rr] += v0 * w0 + v1 * w1;
                }
        }
#pragma unroll
        for (int mf = 0; mf < 2; mf++)
#pragma unroll
            for (int rr = 0; rr < 2; rr++) {
                s[mf][rr] += __shfl_xor_sync(0xffffffffu, s[mf][rr], 1);
                s[mf][rr] += __shfl_xor_sync(0xffffffffu, s[mf][rr], 2);
            }
        if (t == 0) {
            float* hz = aux + (long)z * HW_;
#pragma unroll
            for (int mf = 0; mf < 2; mf++)
#pragma unroll
                for (int rr = 0; rr < 2; rr++) {
                    int gm = m0 + wm * 32 + mf * 16 + rr * 8 + g;
                    if (gm < M) atomicAdd(hz + gm, s[mf][rr]);
                }
        }
        return;
    }

    if (EPI == 0) Cm += z1 * sC1 + z2 * sC2;
    else          Ch += z1 * sC1 + z2 * sC2;

    float gs[2][2]  = {{0.f, 0.f}, {0.f, 0.f}};
    float gs2[2][2] = {{0.f, 0.f}, {0.f, 0.f}};

#pragma unroll
    for (int mf = 0; mf < 2; mf++) {
#pragma unroll
        for (int nf = 0; nf < 8; nf++) {
            const float* d = acc[mf][nf];
            int gm0 = m0 + wm * 32 + mf * 16 + g;
            int gn  = n0 + wn * 64 + nf * 8 + 2 * t;
            if (gn >= N) continue;
            float bc0 = 0.f, bc1 = 0.f;
            if (BIAS_MODE == 1) { bc0 = bptr[gn]; bc1 = bptr[gn + 1]; }
#pragma unroll
            for (int rr = 0; rr < 2; rr++) {
                int gm = gm0 + rr * 8;
                if (gm >= M) continue;
                float v0 = d[rr * 2 + 0], v1 = d[rr * 2 + 1];
                if (BIAS_MODE == 1) { v0 += bc0; v1 += bc1; }
                else { float br = bptr[gm]; v0 += br; v1 += br; }
                long idx = (long)gm * ldc + gn;
                if (EPI == 0) {
                    *reinterpret_cast<float2*>(Cm + idx) = make_float2(v0, v1);
                } else {
                    __half h0 = __float2half_rn(v0), h1 = __float2half_rn(v1);
                    *reinterpret_cast<uint32_t*>(Ch + idx) =
                        (uint32_t)__half_as_ushort(h0) | ((uint32_t)__half_as_ushort(h1) << 16);
                }
                if (EPI == 3) {
                    gs[mf][rr]  += v0 + v1;
                    gs2[mf][rr] += v0 * v0 + v1 * v1;
                }
            }
        }
    }

    if (EPI == 3) {
#pragma unroll
        for (int mf = 0; mf < 2; mf++)
#pragma unroll
            for (int rr = 0; rr < 2; rr++) {
#pragma unroll
                for (int o = 16; o; o >>= 1) {
                    gs[mf][rr]  += __shfl_xor_sync(0xffffffffu, gs[mf][rr],  o);
                    gs2[mf][rr] += __shfl_xor_sync(0xffffffffu, gs2[mf][rr], o);
                }
                if (lane == 0) {
                    int gidx = (m0 + wm * 32 + mf * 16 + rr * 8) >> 3;   // 0..31
                    atomicAdd(aux + (z1 * 32 + gidx) * 2 + 0, gs[mf][rr]);
                    atomicAdd(aux + (z1 * 32 + gidx) * 2 + 1, gs2[mf][rr]);
                }
            }
    }
}

// ---------------- prep: convert weights + zero accumulators ------------------
__global__ void prep_kernel(const float* __restrict__ ef_w,
                            const float* __restrict__ hm1_w,
                            const float* __restrict__ merge_w,
                            __half* __restrict__ w_h,
                            __half* __restrict__ mw_h,
                            float* __restrict__ hacc, float* __restrict__ stat2)
{
    int i = blockIdx.x * 256 + threadIdx.x;
    if (i < DEXP * C_)    w_h[WOFF_EF + i]  = __float2half_rn(ef_w[i]);
    if (i < P_ * C_ * C_) w_h[WOFF_HM1 + i] = __float2half_rn(hm1_w[i]);
    if (i < C_ * DEXP)    mw_h[i] = __float2half_rn(merge_w[i]);
    if (i < B_ * P_ * HW_) hacc[i] = 0.f;
    if (i < B_ * 32 * 2)   stat2[i] = 0.f;
}

// -------- transpose x (B,C,HW) -> fp16 plane (B,HW,C), uint2 stores ----------
__global__ void split_x_kernel(const float* __restrict__ x, __half* __restrict__ xh)
{
    __shared__ float tile[32][33];
    int b = blockIdx.z;
    int hw0 = blockIdx.x * 32, c0 = blockIdx.y * 32;
    const float* xb = x + (long)b * C_ * HW_;
    int tx = threadIdx.x, ty = threadIdx.y;   // 32 x 8
#pragma unroll
    for (int i = 0; i < 32; i += 8) {
        int c = c0 + ty + i, hw = hw0 + tx;
        tile[ty + i][tx] = (hw < HW_) ? xb[(long)c * HW_ + hw] : 0.f;
    }
    __syncthreads();
    int tid = ty * 32 + tx;
    int cq   = tid & 7;
    int hwl0 = tid >> 3;
    {
        int hwl = hwl0;
        int hw = hw0 + hwl;
        if (hw < HW_) {
            __half h0 = __float2half_rn(tile[4 * cq + 0][hwl]);
            __half h1 = __float2half_rn(tile[4 * cq + 1][hwl]);
            __half h2 = __float2half_rn(tile[4 * cq + 2][hwl]);
            __half h3 = __float2half_rn(tile[4 * cq + 3][hwl]);
            long idx = (long)b * HW_ * C_ + (long)hw * C_ + c0 + 4 * cq;
            uint2 v;
            v.x = (uint32_t)__half_as_ushort(h0) | ((uint32_t)__half_as_ushort(h1) << 16);
            v.y = (uint32_t)__half_as_ushort(h2) | ((uint32_t)__half_as_ushort(h3) << 16);
            *reinterpret_cast<uint2*>(xh + idx) = v;
        }
    }
}

__global__ void heat_exp_kernel(const float* __restrict__ hacc,
                                const float* __restrict__ hm2_b,
                                float* __restrict__ heat)
{
    int i = blockIdx.x * 256 + threadIdx.x;
    if (i >= B_ * P_ * HW_) return;
    int p = (i / HW_) % P_;
    heat[i] = expf(hacc[i] + hm2_b[p]);
}

// --------- deformable bilinear gather: fp16 source ---------------------------
__global__ void sample_kernel(const __half* __restrict__ efs,  // (B, HW, 512) fp16
                              const float* __restrict__ heat,  // (B*P, HW)
                              const float* __restrict__ offs,  // (B, P*KB*2, HW)
                              __half* __restrict__ oh)         // fp16 out (B,HW,512)
{
    int gw = (blockIdx.x * blockDim.x + threadIdx.x) >> 5;
    int lane = threadIdx.x & 31;
    if (gw >= B_ * P_ * HW_) return;
    int i  = gw % HW_;
    int bp = gw / HW_;
    int p  = bp % P_;
    int b  = bp / P_;
    int y = i / W_, x = i % W_;

    const uint4* efb = reinterpret_cast<const uint4*>(
        efs + ((long)b * HW_) * DEXP + p * C_ + lane * 8);
    const float* heatb = heat + (long)bp * HW_;
    const float* offb  = offs + ((long)b * (P_ * KB_ * 2) + p * KB_ * 2) * HW_;

    float ys[KB_], xs[KB_];
#pragma unroll
    for (int k = 0; k < KB_; k++) {
        ys[k] = (float)y + offb[(k * 2 + 0) * HW_ + i];
        xs[k] = (float)x + offb[(k * 2 + 1) * HW_ + i];
    }

    float n[8];
#pragma unroll
    for (int j = 0; j < 8; j++) n[j] = 0.f;
    float den = 0.f;

#pragma unroll
    for (int k = 0; k < KB_; k++) {
        float y0f = floorf(ys[k]), x0f = floorf(xs[k]);
#pragma unroll
        for (int c4 = 0; c4 < 4; c4++) {
            float yi = y0f + (float)(c4 >> 1);
            float xi = x0f + (float)(c4 & 1);
            if (yi < 0.f || yi > (float)(H_ - 1) || xi < 0.f || xi > (float)(W_ - 1))
                continue;
            float w = (1.f - fabsf(ys[k] - yi)) * (1.f - fabsf(xs[k] - xi));
            int src = (int)yi * W_ + (int)xi;
            float wh = w * heatb[src];
            den += wh;
            uint4 u = efb[(long)src * (DEXP / 8)];
            float2 f0 = __half22float2(*reinterpret_cast<__half2*>(&u.x));
            float2 f1 = __half22float2(*reinterpret_cast<__half2*>(&u.y));
            float2 f2 = __half22float2(*reinterpret_cast<__half2*>(&u.z));
            float2 f3 = __half22float2(*reinterpret_cast<__half2*>(&u.w));
            n[0] += wh * f0.x; n[1] += wh * f0.y;
            n[2] += wh * f1.x; n[3] += wh * f1.y;
            n[4] += wh * f2.x; n[5] += wh * f2.y;
            n[6] += wh * f3.x; n[7] += wh * f3.y;
        }
    }
    float inv = 1.f / (den + 1e-6f);
    unsigned short hh[8];
#pragma unroll
    for (int j = 0; j < 8; j++) hh[j] = __half_as_ushort(__float2half_rn(n[j] * inv));
    uint4 ph;
    ph.x = (uint32_t)hh[0] | ((uint32_t)hh[1] << 16);
    ph.y = (uint32_t)hh[2] | ((uint32_t)hh[3] << 16);
    ph.z = (uint32_t)hh[4] | ((uint32_t)hh[5] << 16);
    ph.w = (uint32_t)hh[6] | ((uint32_t)hh[7] << 16);
    long obase = ((long)b * HW_ + i) * DEXP + p * C_ + lane * 8;
    *reinterpret_cast<uint4*>(oh + obase) = ph;
}

// ---------------- GroupNorm finalize (fp16 merged, stats precomputed) --------
__global__ void gn_norm(const __half* __restrict__ merged,
                        const float* __restrict__ stat2,
                        const float* __restrict__ gn_g,
                        const float* __restrict__ gn_b,
                        float* __restrict__ out)
{
    long i4 = (long)blockIdx.x * 256 + threadIdx.x;
    const long total4 = (long)B_ * C_ * HW_ / 4;
    if (i4 >= total4) return;
    long idx = i4 * 4;
    int c = (int)((idx / HW_) % C_);
    int b = (int)(idx / ((long)C_ * HW_));
    int g = c >> 3;
    const float n = 8.f * HW_;
    float s  = stat2[(b * 32 + g) * 2 + 0];
    float s2 = stat2[(b * 32 + g) * 2 + 1];
    float mu   = s / n;
    float var  = s2 / n - mu * mu;
    float rstd = rsqrtf(var + 1e-5f);
    float sc = rstd * gn_g[c];
    float sh = gn_b[c] - mu * sc;
    uint2 u = *reinterpret_cast<const uint2*>(merged + idx);
    float2 v0 = __half22float2(*reinterpret_cast<__half2*>(&u.x));
    float2 v1 = __half22float2(*reinterpret_cast<__half2*>(&u.y));
    float4 r;
    r.x = fmaxf(v0.x * sc + sh, 0.f);
    r.y = fmaxf(v0.y * sc + sh, 0.f);
    r.z = fmaxf(v1.x * sc + sh, 0.f);
    r.w = fmaxf(v1.y * sc + sh, 0.f);
    *reinterpret_cast<float4*>(out + idx) = r;
}

// ---------------- launch ------------------------------------------------------
extern "C" void kernel_launch(void* const* d_in, const int* in_sizes, int n_in,
                              void* d_out, int out_size)
{
    const float* x       = (const float*)d_in[0];
    const float* offsets = (const float*)d_in[1];
    const float* ef_w    = (const float*)d_in[2];
    const float* ef_b    = (const float*)d_in[3];
    const float* hm1_w   = (const float*)d_in[4];
    const float* hm1_b   = (const float*)d_in[5];
    const float* hm2_w   = (const float*)d_in[6];
    const float* hm2_b   = (const float*)d_in[7];
    const float* merge_w = (const float*)d_in[8];
    const float* merge_b = (const float*)d_in[9];
    const float* gn_g    = (const float*)d_in[10];
    const float* gn_b    = (const float*)d_in[11];
    float* out = (float*)d_out;

    float *heat, *hacc, *stat2;
    __half *efs_h, *out_h, *xs_h, *w_h, *mw_h, *merged;
    cudaGetSymbolAddress((void**)&efs_h,  g_efs_h);
    cudaGetSymbolAddress((void**)&out_h,  g_out_h);
    cudaGetSymbolAddress((void**)&xs_h,   g_xs_h);
    cudaGetSymbolAddress((void**)&w_h,    g_w_h);
    cudaGetSymbolAddress((void**)&mw_h,   g_mw_h);
    cudaGetSymbolAddress((void**)&heat,   g_heat);
    cudaGetSymbolAddress((void**)&hacc,   g_hacc);
    cudaGetSymbolAddress((void**)&merged, g_merged);
    cudaGetSymbolAddress((void**)&stat2,  g_stat2);

    cudaFuncSetAttribute(tc_gemm<1, 1>, cudaFuncAttributeMaxDynamicSharedMemorySize, GEMM_SMEM);
    cudaFuncSetAttribute(tc_gemm<1, 2>, cudaFuncAttributeMaxDynamicSharedMemorySize, GEMM_SMEM);
    cudaFuncSetAttribute(tc_gemm<2, 3>, cudaFuncAttributeMaxDynamicSharedMemorySize, GEMM_SMEM);

    // 0) prep: weight conversion + zeroing; x transpose->fp16
    prep_kernel<<<(DEXP * C_ + 255) / 256, 256>>>(ef_w, hm1_w, merge_w,
                                                  w_h, mw_h, hacc, stat2);
    {
        dim3 grid((HW_ + 31) / 32, C_ / 32, B_);
        split_x_kernel<<<grid, dim3(32, 8)>>>(x, xs_h);
    }

    // 1) GEMM1: efs[b][i][d] = fp16( sum_c xT[b][i][c]*ef_w[d][c] + ef_b[d] )
    {
        dim3 grid(DEXP / GBN, (HW_ + GBM - 1) / GBM, B_);
        tc_gemm<1, 1><<<grid, 256, GEMM_SMEM>>>(
            xs_h, C_, (long)HW_ * C_, 0,
            w_h + WOFF_EF, C_, 0, 0,
            nullptr, DEXP, (long)HW_ * DEXP, 0,
            ef_b, 0, 0,
            efs_h, nullptr, nullptr,
            1, HW_, DEXP, C_);
    }

    // 2) GEMM2 + heat fusion
    {
        dim3 grid(C_ / GBN, (HW_ + GBM - 1) / GBM, B_ * P_);
        tc_gemm<1, 2><<<grid, 256, GEMM_SMEM>>>(
            efs_h, DEXP, (long)HW_ * DEXP, (long)C_,
            w_h + WOFF_HM1, C_, 0, (long)C_ * C_,
            nullptr, 0, 0, 0,
            hm1_b, 0, (long)C_,
            nullptr, hm2_w, hacc,
            P_, HW_, C_, C_);
    }

    // 3) heat = exp(hacc + hm2_b)
    heat_exp_kernel<<<(B_ * P_ * HW_ + 255) / 256, 256>>>(hacc, hm2_b, heat);

    // 4) gather (fp16 source) -> fp16 outs
    {
        int warps = B_ * P_ * HW_;
        sample_kernel<<<(warps * 32 + 255) / 256, 256>>>(efs_h, heat, offsets, out_h);
    }

    // 5) GEMM3 + GN stats -> fp16 merged
    {
        dim3 grid((HW_ + GBN - 1) / GBN, C_ / GBM, B_);
        tc_gemm<2, 3><<<grid, 256, GEMM_SMEM>>>(
            mw_h, DEXP, 0, 0,
            out_h, DEXP, (long)HW_ * DEXP, 0,
            nullptr, HW_, (long)C_ * HW_, 0,
            merge_b, 0, 0,
            merged, nullptr, stat2,
            1, C_, HW_, DEXP);
    }

    // 6) GroupNorm finalize + ReLU
    {
        long total4 = (long)B_ * C_ * HW_ / 4;
        gn_norm<<<(int)((total4 + 255) / 256), 256>>>(merged, stat2, gn_g, gn_b, out);
    }
}

// round 16
// speedup vs baseline: 1.2523x; 1.0417x over previous
#include <cuda_runtime.h>
#include <cuda_fp16.h>
#include <cstdint>
#include <math.h>

#define B_   2
#define C_   256
#define H_   100
#define W_   152
#define HW_  (H_*W_)
#define P_   2
#define KB_  5          // bins
#define DEXP (P_*C_)    // 512

// ---------------- scratch (static device memory; no allocation) -------------
__device__ __half   g_efs_h[(size_t)B_*HW_*DEXP];   // ef fp16 (GEMM2 A + gather src)
__device__ __half   g_out_h[(size_t)B_*HW_*DEXP];   // gather out fp16 (GEMM3 B)
__device__ __half   g_xs_h [(size_t)B_*HW_*C_];     // x transposed fp16 (GEMM1 A)
#define WOFF_EF   0
#define WOFF_HM1  (DEXP*C_)                  // 131072
__device__ __half   g_w_h  [DEXP*C_ + P_*C_*C_];    // ef_w, hm1_w fp16 (B operands)
__device__ __half   g_mw_h [C_*DEXP];               // merge_w fp16 (GEMM3 A)
__device__ float  g_heat [B_*P_*HW_];
__device__ float  g_hacc [B_*P_*HW_];
__device__ __half g_merged[(size_t)B_*C_*HW_];      // merged fp16 (GN input)
__device__ float  g_stat2[B_*32*2];          // (b,g) -> sum, sumsq (atomic)

// ======================= helpers =============================================
__device__ __forceinline__ uint32_t smem_u32(const void* p) {
    uint32_t a;
    asm("{ .reg .u64 t; cvta.to.shared.u64 t, %1; cvt.u32.u64 %0, t; }" : "=r"(a) : "l"(p));
    return a;
}
__device__ __forceinline__ void ldsm_x4(uint32_t* r, uint32_t a) {
    asm volatile("ldmatrix.sync.aligned.m8n8.x4.shared.b16 {%0,%1,%2,%3}, [%4];"
        : "=r"(r[0]), "=r"(r[1]), "=r"(r[2]), "=r"(r[3]) : "r"(a));
}
__device__ __forceinline__ void mma_f16(float* d, const uint32_t* a, const uint32_t* b) {
    asm volatile("mma.sync.aligned.m16n8k16.row.col.f32.f16.f16.f32 "
        "{%0,%1,%2,%3}, {%4,%5,%6,%7}, {%8,%9}, {%0,%1,%2,%3};"
        : "+f"(d[0]), "+f"(d[1]), "+f"(d[2]), "+f"(d[3])
        : "r"(a[0]), "r"(a[1]), "r"(a[2]), "r"(a[3]), "r"(b[0]), "r"(b[1]));
}
__device__ __forceinline__ void cp_async16(uint32_t dst, const void* src, int src_bytes) {
    asm volatile("cp.async.cg.shared.global [%0], [%1], 16, %2;"
        :: "r"(dst), "l"(src), "r"(src_bytes) : "memory");
}
#define CP_COMMIT() asm volatile("cp.async.commit_group;" ::: "memory")
#define CP_WAIT(n)  asm volatile("cp.async.wait_group %0;" :: "n"(n) : "memory")

// ================= single-pass fp16 mma.sync GEMM (frozen config) ============
// D[M,N] = A[M,K] * B[N,K]^T;  A, B plain fp16 planes, K-major.
// 128x128 CTA tile, warp tile 32x64 (4 M-warps x 2 N-warps), 2 CTAs/SM.
// GBK=64, 2-stage cp.async ring, prefetch distance 1, 1 barrier per K-tile.
// EPI: 0 = fp32 C (+bias);
//      1 = fp16 C plane (GEMM1);
//      2 = no C store; heat fusion: atomicAdd( sum_n relu(c+bias)*w2[n] );
//      3 = fp16 C plane + atomic GN sums from fp32 values (GEMM3).
#define GBM 128
#define GBN 128
#define GBK 64
#define ROWB   144                 // 64 halfs + 16B pad; LDSM conflict-free
#define ATILE_B (128*ROWB)         // 18432
#define BTILE_B (128*ROWB)         // 18432
#define BUF_B  (ATILE_B + BTILE_B) // 36864
#define NSTAGE 2
#define GEMM_SMEM (NSTAGE*BUF_B)   // 73728 B

template<int BIAS_MODE, int EPI>
__global__ __launch_bounds__(256, 2)
void tc_gemm(const __half* __restrict__ Ahp, int lda, long sA1, long sA2,
             const __half* __restrict__ Bhp, int ldb, long sB1, long sB2,
             float* __restrict__ Cm, int ldc, long sC1, long sC2,
             const float* __restrict__ bias, long sb1, long sb2,
             __half* __restrict__ Ch,
             const float* __restrict__ w2, float* __restrict__ aux,
             int zdiv, int M, int N, int K)
{
    extern __shared__ char smem[];
    const uint32_t sbase = smem_u32(smem);
    const int tid = threadIdx.x;
    const int lane = tid & 31, wid = tid >> 5;

    const int z = blockIdx.z;
    const int z1 = z / zdiv, z2 = z % zdiv;
    Ahp += z1 * sA1 + z2 * sA2;
    Bhp += z1 * sB1 + z2 * sB2;
    const float* bptr = bias + z1 * sb1 + z2 * sb2;

    const int m0 = blockIdx.y * GBM;
    const int n0 = blockIdx.x * GBN;

    const int wm = wid & 3;          // 4 warps over M (32 rows each)
    const int wn = wid >> 2;         // 2 warps over N (64 cols each)
    const int lane8 = lane & 7, sel = lane >> 3;

    float acc[2][8][4];
#pragma unroll
    for (int i = 0; i < 2; i++)
#pragma unroll
        for (int j = 0; j < 8; j++)
#pragma unroll
            for (int q = 0; q < 4; q++) acc[i][j][q] = 0.f;

    const int nk = K / GBK;

    auto LOADCP = [&](int kt, int stage) {
        const int k0 = kt * GBK;
        const uint32_t sb = sbase + stage * BUF_B;
#pragma unroll
        for (int j = 0; j < 4; j++) {
            int idx = tid + j * 256;           // 0..1023
            int row = idx >> 3, q = idx & 7;   // 8 quads of 16B per 64-K row
            uint32_t off = (uint32_t)(row * ROWB + q * 16);
            int gm = m0 + row, gn = n0 + row;
            int szA = (gm < M) ? 16 : 0;
            int szB = (gn < N) ? 16 : 0;
            long ga = (long)(gm < M ? gm : M - 1) * lda + k0 + q * 8;
            long gb = (long)(gn < N ? gn : N - 1) * ldb + k0 + q * 8;
            cp_async16(sb + off,           Ahp + ga, szA);
            cp_async16(sb + ATILE_B + off, Bhp + gb, szB);
        }
    };

    auto COMPUTE = [&](int stage) {
        const uint32_t ah_b = sbase + stage * BUF_B;
        const uint32_t bh_b = ah_b + ATILE_B;
#pragma unroll
        for (int ks = 0; ks < 4; ks++) {
            const int kb = ks * 16;
            uint32_t ah[2][4];
#pragma unroll
            for (int mf = 0; mf < 2; mf++) {
                int row = wm * 32 + mf * 16 + lane8 + (sel & 1) * 8;
                int kc  = kb + (sel & 2) * 4;
                ldsm_x4(ah[mf], ah_b + (uint32_t)(row * ROWB + kc * 2));
            }
#pragma unroll
            for (int nf2 = 0; nf2 < 4; nf2++) {
                int nrow = wn * 64 + nf2 * 16 + lane8 + (sel & 2) * 4;
                int kc   = kb + (sel & 1) * 8;
                uint32_t bh4[4];
                ldsm_x4(bh4, bh_b + (uint32_t)(nrow * ROWB + kc * 2));
#pragma unroll
                for (int half = 0; half < 2; half++)
#pragma unroll
                    for (int mf = 0; mf < 2; mf++)
                        mma_f16(acc[mf][nf2 * 2 + half], ah[mf], bh4 + half * 2);
            }
        }
    };

    // 2-stage pipeline, prefetch distance 1, one barrier per K-tile
    LOADCP(0, 0); CP_COMMIT();
    for (int kt = 0; kt < nk; kt++) {
        CP_WAIT(0);
        __syncthreads();
        if (kt + 1 < nk) { LOADCP(kt + 1, (kt + 1) & 1); CP_COMMIT(); }
        COMPUTE(kt & 1);
    }

    // ---- epilogue ----
    const int g = lane >> 2, t = lane & 3;

    if (EPI == 2) {
        const float* w2p = w2 + z2 * C_;
        float s[2][2] = {{0.f, 0.f}, {0.f, 0.f}};
#pragma unroll
        for (int nf = 0; nf < 8; nf++) {
            int gn = n0 + wn * 64 + nf * 8 + 2 * t;
            float b0 = bptr[gn], b1 = bptr[gn + 1];
            float w0 = w2p[gn],  w1 = w2p[gn + 1];
#pragma unroll
            for (int mf = 0; mf < 2; mf++)
#pragma unroll
                for (int rr = 0; rr < 2; rr++) {
                    float v0 = fmaxf(acc[mf][nf][rr * 2 + 0] + b0, 0.f);
                    float v1 = fmaxf(acc[mf][nf][rr * 2 + 1] + b1, 0.f);
                    s[mf][rr] += v0 * w0 + v1 * w1;
                }
        }
#pragma unroll
        for (int mf = 0; mf < 2; mf++)
#pragma unroll
            for (int rr = 0; rr < 2; rr++) {
                s[mf][rr] += __shfl_xor_sync(0xffffffffu, s[mf][rr], 1);
                s[mf][rr] += __shfl_xor_sync(0xffffffffu, s[mf][rr], 2);
            }
        if (t == 0) {
            float* hz = aux + (long)z * HW_;
#pragma unroll
            for (int mf = 0; mf < 2; mf++)
#pragma unroll
                for (int rr = 0; rr < 2; rr++) {
                    int gm = m0 + wm * 32 + mf * 16 + rr * 8 + g;
                    if (gm < M) atomicAdd(hz + gm, s[mf][rr]);
                }
        }
        return;
    }

    if (EPI == 0) Cm += z1 * sC1 + z2 * sC2;
    else          Ch += z1 * sC1 + z2 * sC2;

    float gs[2][2]  = {{0.f, 0.f}, {0.f, 0.f}};
    float gs2[2][2] = {{0.f, 0.f}, {0.f, 0.f}};

#pragma unroll
    for (int mf = 0; mf < 2; mf++) {
#pragma unroll
        for (int nf = 0; nf < 8; nf++) {
            const float* d = acc[mf][nf];
            int gm0 = m0 + wm * 32 + mf * 16 + g;
            int gn  = n0 + wn * 64 + nf * 8 + 2 * t;
            if (gn >= N) continue;
            float bc0 = 0.f, bc1 = 0.f;
            if (BIAS_MODE == 1) { bc0 = bptr[gn]; bc1 = bptr[gn + 1]; }
#pragma unroll
            for (int rr = 0; rr < 2; rr++) {
                int gm = gm0 + rr * 8;
                if (gm >= M) continue;
                float v0 = d[rr * 2 + 0], v1 = d[rr * 2 + 1];
                if (BIAS_MODE == 1) { v0 += bc0; v1 += bc1; }
                else { float br = bptr[gm]; v0 += br; v1 += br; }
                long idx = (long)gm * ldc + gn;
                if (EPI == 0) {
                    *reinterpret_cast<float2*>(Cm + idx) = make_float2(v0, v1);
                } else {
                    __half h0 = __float2half_rn(v0), h1 = __float2half_rn(v1);
                    *reinterpret_cast<uint32_t*>(Ch + idx) =
                        (uint32_t)__half_as_ushort(h0) | ((uint32_t)__half_as_ushort(h1) << 16);
                }
                if (EPI == 3) {
                    gs[mf][rr]  += v0 + v1;
                    gs2[mf][rr] += v0 * v0 + v1 * v1;
                }
            }
        }
    }

    if (EPI == 3) {
#pragma unroll
        for (int mf = 0; mf < 2; mf++)
#pragma unroll
            for (int rr = 0; rr < 2; rr++) {
#pragma unroll
                for (int o = 16; o; o >>= 1) {
                    gs[mf][rr]  += __shfl_xor_sync(0xffffffffu, gs[mf][rr],  o);
                    gs2[mf][rr] += __shfl_xor_sync(0xffffffffu, gs2[mf][rr], o);
                }
                if (lane == 0) {
                    int gidx = (m0 + wm * 32 + mf * 16 + rr * 8) >> 3;   // 0..31
                    atomicAdd(aux + (z1 * 32 + gidx) * 2 + 0, gs[mf][rr]);
                    atomicAdd(aux + (z1 * 32 + gidx) * 2 + 1, gs2[mf][rr]);
                }
            }
    }
}

// ---------------- prep: convert weights + zero accumulators ------------------
__global__ void prep_kernel(const float* __restrict__ ef_w,
                            const float* __restrict__ hm1_w,
                            const float* __restrict__ merge_w,
                            __half* __restrict__ w_h,
                            __half* __restrict__ mw_h,
                            float* __restrict__ hacc, float* __restrict__ stat2)
{
    int i = blockIdx.x * 256 + threadIdx.x;
    if (i < DEXP * C_)    w_h[WOFF_EF + i]  = __float2half_rn(ef_w[i]);
    if (i < P_ * C_ * C_) w_h[WOFF_HM1 + i] = __float2half_rn(hm1_w[i]);
    if (i < C_ * DEXP)    mw_h[i] = __float2half_rn(merge_w[i]);
    if (i < B_ * P_ * HW_) hacc[i] = 0.f;
    if (i < B_ * 32 * 2)   stat2[i] = 0.f;
}

// -------- transpose x (B,C,HW) -> fp16 plane (B,HW,C), uint2 stores ----------
__global__ void split_x_kernel(const float* __restrict__ x, __half* __restrict__ xh)
{
    __shared__ float tile[32][33];
    int b = blockIdx.z;
    int hw0 = blockIdx.x * 32, c0 = blockIdx.y * 32;
    const float* xb = x + (long)b * C_ * HW_;
    int tx = threadIdx.x, ty = threadIdx.y;   // 32 x 8
#pragma unroll
    for (int i = 0; i < 32; i += 8) {
        int c = c0 + ty + i, hw = hw0 + tx;
        tile[ty + i][tx] = (hw < HW_) ? xb[(long)c * HW_ + hw] : 0.f;
    }
    __syncthreads();
    int tid = ty * 32 + tx;
    int cq   = tid & 7;
    int hwl0 = tid >> 3;
    {
        int hwl = hwl0;
        int hw = hw0 + hwl;
        if (hw < HW_) {
            __half h0 = __float2half_rn(tile[4 * cq + 0][hwl]);
            __half h1 = __float2half_rn(tile[4 * cq + 1][hwl]);
            __half h2 = __float2half_rn(tile[4 * cq + 2][hwl]);
            __half h3 = __float2half_rn(tile[4 * cq + 3][hwl]);
            long idx = (long)b * HW_ * C_ + (long)hw * C_ + c0 + 4 * cq;
            uint2 v;
            v.x = (uint32_t)__half_as_ushort(h0) | ((uint32_t)__half_as_ushort(h1) << 16);
            v.y = (uint32_t)__half_as_ushort(h2) | ((uint32_t)__half_as_ushort(h3) << 16);
            *reinterpret_cast<uint2*>(xh + idx) = v;
        }
    }
}

__global__ void heat_exp_kernel(const float* __restrict__ hacc,
                                const float* __restrict__ hm2_b,
                                float* __restrict__ heat)
{
    int i = blockIdx.x * 256 + threadIdx.x;
    if (i >= B_ * P_ * HW_) return;
    int p = (i / HW_) % P_;
    heat[i] = expf(hacc[i] + hm2_b[p]);
}

// --------- deformable bilinear gather: factored corner math ------------------
__global__ void sample_kernel(const __half* __restrict__ efs,  // (B, HW, 512) fp16
                              const float* __restrict__ heat,  // (B*P, HW)
                              const float* __restrict__ offs,  // (B, P*KB*2, HW)
                              __half* __restrict__ oh)         // fp16 out (B,HW,512)
{
    int gw = (blockIdx.x * blockDim.x + threadIdx.x) >> 5;
    int lane = threadIdx.x & 31;
    if (gw >= B_ * P_ * HW_) return;
    int i  = gw % HW_;
    int bp = gw / HW_;
    int p  = bp % P_;
    int b  = bp / P_;
    int y = i / W_, x = i % W_;

    const uint4* efb = reinterpret_cast<const uint4*>(
        efs + ((long)b * HW_) * DEXP + p * C_ + lane * 8);
    const float* heatb = heat + (long)bp * HW_;
    const float* offb  = offs + ((long)b * (P_ * KB_ * 2) + p * KB_ * 2) * HW_;

    float ys[KB_], xs[KB_];
#pragma unroll
    for (int k = 0; k < KB_; k++) {
        ys[k] = (float)y + offb[(k * 2 + 0) * HW_ + i];
        xs[k] = (float)x + offb[(k * 2 + 1) * HW_ + i];
    }

    float n[8];
#pragma unroll
    for (int j = 0; j < 8; j++) n[j] = 0.f;
    float den = 0.f;

#define GACC(SRC, WT) do {                                                 \
        float wh = (WT) * heatb[(SRC)];                                    \
        den += wh;                                                         \
        uint4 u = efb[(long)(SRC) * (DEXP / 8)];                           \
        float2 f0 = __half22float2(*reinterpret_cast<__half2*>(&u.x));     \
        float2 f1 = __half22float2(*reinterpret_cast<__half2*>(&u.y));     \
        float2 f2 = __half22float2(*reinterpret_cast<__half2*>(&u.z));     \
        float2 f3 = __half22float2(*reinterpret_cast<__half2*>(&u.w));     \
        n[0] += wh * f0.x; n[1] += wh * f0.y;                              \
        n[2] += wh * f1.x; n[3] += wh * f1.y;                              \
        n[4] += wh * f2.x; n[5] += wh * f2.y;                              \
        n[6] += wh * f3.x; n[7] += wh * f3.y;                              \
    } while (0)

#pragma unroll
    for (int k = 0; k < KB_; k++) {
        float y0f = floorf(ys[k]), x0f = floorf(xs[k]);
        float fy = ys[k] - y0f, fx = xs[k] - x0f;
        float gy = 1.f - fy,    gx = 1.f - fx;
        int y0 = (int)y0f, x0 = (int)x0f;
        int base = y0 * W_ + x0;
        bool vy0 = (y0 >= 0)  && (y0 <= H_ - 1);
        bool vy1 = (y0 >= -1) && (y0 <= H_ - 2);
        bool vx0 = (x0 >= 0)  && (x0 <= W_ - 1);
        bool vx1 = (x0 >= -1) && (x0 <= W_ - 2);
        if (vy0 && vx0) GACC(base,          gy * gx);
        if (vy0 && vx1) GACC(base + 1,      gy * fx);
        if (vy1 && vx0) GACC(base + W_,     fy * gx);
        if (vy1 && vx1) GACC(base + W_ + 1, fy * fx);
    }
#undef GACC

    float inv = 1.f / (den + 1e-6f);
    unsigned short hh[8];
#pragma unroll
    for (int j = 0; j < 8; j++) hh[j] = __half_as_ushort(__float2half_rn(n[j] * inv));
    uint4 ph;
    ph.x = (uint32_t)hh[0] | ((uint32_t)hh[1] << 16);
    ph.y = (uint32_t)hh[2] | ((uint32_t)hh[3] << 16);
    ph.z = (uint32_t)hh[4] | ((uint32_t)hh[5] << 16);
    ph.w = (uint32_t)hh[6] | ((uint32_t)hh[7] << 16);
    long obase = ((long)b * HW_ + i) * DEXP + p * C_ + lane * 8;
    *reinterpret_cast<uint4*>(oh + obase) = ph;
}

// ---------------- GroupNorm finalize (fp16 merged, stats precomputed) --------
__global__ void gn_norm(const __half* __restrict__ merged,
                        const float* __restrict__ stat2,
                        const float* __restrict__ gn_g,
                        const float* __restrict__ gn_b,
                        float* __restrict__ out)
{
    long i4 = (long)blockIdx.x * 256 + threadIdx.x;
    const long total4 = (long)B_ * C_ * HW_ / 4;
    if (i4 >= total4) return;
    long idx = i4 * 4;
    int c = (int)((idx / HW_) % C_);
    int b = (int)(idx / ((long)C_ * HW_));
    int g = c >> 3;
    const float n = 8.f * HW_;
    float s  = stat2[(b * 32 + g) * 2 + 0];
    float s2 = stat2[(b * 32 + g) * 2 + 1];
    float mu   = s / n;
    float var  = s2 / n - mu * mu;
    float rstd = rsqrtf(var + 1e-5f);
    float sc = rstd * gn_g[c];
    float sh = gn_b[c] - mu * sc;
    uint2 u = *reinterpret_cast<const uint2*>(merged + idx);
    float2 v0 = __half22float2(*reinterpret_cast<__half2*>(&u.x));
    float2 v1 = __half22float2(*reinterpret_cast<__half2*>(&u.y));
    float4 r;
    r.x = fmaxf(v0.x * sc + sh, 0.f);
    r.y = fmaxf(v0.y * sc + sh, 0.f);
    r.z = fmaxf(v1.x * sc + sh, 0.f);
    r.w = fmaxf(v1.y * sc + sh, 0.f);
    *reinterpret_cast<float4*>(out + idx) = r;
}

// ---------------- launch ------------------------------------------------------
extern "C" void kernel_launch(void* const* d_in, const int* in_sizes, int n_in,
                              void* d_out, int out_size)
{
    const float* x       = (const float*)d_in[0];
    const float* offsets = (const float*)d_in[1];
    const float* ef_w    = (const float*)d_in[2];
    const float* ef_b    = (const float*)d_in[3];
    const float* hm1_w   = (const float*)d_in[4];
    const float* hm1_b   = (const float*)d_in[5];
    const float* hm2_w   = (const float*)d_in[6];
    const float* hm2_b   = (const float*)d_in[7];
    const float* merge_w = (const float*)d_in[8];
    const float* merge_b = (const float*)d_in[9];
    const float* gn_g    = (const float*)d_in[10];
    const float* gn_b    = (const float*)d_in[11];
    float* out = (float*)d_out;

    float *heat, *hacc, *stat2;
    __half *efs_h, *out_h, *xs_h, *w_h, *mw_h, *merged;
    cudaGetSymbolAddress((void**)&efs_h,  g_efs_h);
    cudaGetSymbolAddress((void**)&out_h,  g_out_h);
    cudaGetSymbolAddress((void**)&xs_h,   g_xs_h);
    cudaGetSymbolAddress((void**)&w_h,    g_w_h);
    cudaGetSymbolAddress((void**)&mw_h,   g_mw_h);
    cudaGetSymbolAddress((void**)&heat,   g_heat);
    cudaGetSymbolAddress((void**)&hacc,   g_hacc);
    cudaGetSymbolAddress((void**)&merged, g_merged);
    cudaGetSymbolAddress((void**)&stat2,  g_stat2);

    cudaFuncSetAttribute(tc_gemm<1, 1>, cudaFuncAttributeMaxDynamicSharedMemorySize, GEMM_SMEM);
    cudaFuncSetAttribute(tc_gemm<1, 2>, cudaFuncAttributeMaxDynamicSharedMemorySize, GEMM_SMEM);
    cudaFuncSetAttribute(tc_gemm<2, 3>, cudaFuncAttributeMaxDynamicSharedMemorySize, GEMM_SMEM);

    // 0) prep: weight conversion + zeroing; x transpose->fp16
    prep_kernel<<<(DEXP * C_ + 255) / 256, 256>>>(ef_w, hm1_w, merge_w,
                                                  w_h, mw_h, hacc, stat2);
    {
        dim3 grid((HW_ + 31) / 32, C_ / 32, B_);
        split_x_kernel<<<grid, dim3(32, 8)>>>(x, xs_h);
    }

    // 1) GEMM1: efs[b][i][d] = fp16( sum_c xT[b][i][c]*ef_w[d][c] + ef_b[d] )
    {
        dim3 grid(DEXP / GBN, (HW_ + GBM - 1) / GBM, B_);
        tc_gemm<1, 1><<<grid, 256, GEMM_SMEM>>>(
            xs_h, C_, (long)HW_ * C_, 0,
            w_h + WOFF_EF, C_, 0, 0,
            nullptr, DEXP, (long)HW_ * DEXP, 0,
            ef_b, 0, 0,
            efs_h, nullptr, nullptr,
            1, HW_, DEXP, C_);
    }

    // 2) GEMM2 + heat fusion
    {
        dim3 grid(C_ / GBN, (HW_ + GBM - 1) / GBM, B_ * P_);
        tc_gemm<1, 2><<<grid, 256, GEMM_SMEM>>>(
            efs_h, DEXP, (long)HW_ * DEXP, (long)C_,
            w_h + WOFF_HM1, C_, 0, (long)C_ * C_,
            nullptr, 0, 0, 0,
            hm1_b, 0, (long)C_,
            nullptr, hm2_w, hacc,
            P_, HW_, C_, C_);
    }

    // 3) heat = exp(hacc + hm2_b)
    heat_exp_kernel<<<(B_ * P_ * HW_ + 255) / 256, 256>>>(hacc, hm2_b, heat);

    // 4) gather (fp16 source) -> fp16 outs
    {
        int warps = B_ * P_ * HW_;
        sample_kernel<<<(warps * 32 + 255) / 256, 256>>>(efs_h, heat, offsets, out_h);
    }

    // 5) GEMM3 + GN stats -> fp16 merged
    {
        dim3 grid((HW_ + GBN - 1) / GBN, C_ / GBM, B_);
        tc_gemm<2, 3><<<grid, 256, GEMM_SMEM>>>(
            mw_h, DEXP, 0, 0,
            out_h, DEXP, (long)HW_ * DEXP, 0,
            nullptr, HW_, (long)C_ * HW_, 0,
            merge_b, 0, 0,
            merged, nullptr, stat2,
            1, C_, HW_, DEXP);
    }

    // 6) GroupNorm finalize + ReLU
    {
        long total4 = (long)B_ * C_ * HW_ / 4;
        gn_norm<<<(int)((total4 + 255) / 256), 256>>>(merged, stat2, gn_g, gn_b, out);
    }
}